// round 14
// baseline (speedup 1.0000x reference)
#include <cuda_runtime.h>
#include <cuda.h>
#include <cuda_bf16.h>
#include <stdint.h>

// Problem constants: B=2, L=2048, E=1024, M_LM=64
#define BATCH 2
#define LSEQ  2048
#define EMB   1024
#define MLM   64
#define NTOK  (BATCH * LSEQ)   // 4096

// GEMM tile config
#define TM 128
#define TN 128
#define KC 32                    // bf16 K elems per chunk (64B row, SW64)
#define GT 256                   // threads per GEMM CTA
#define TILE2 8192               // 128 rows x 64 B
#define STAGE2 (4 * TILE2)       // Ah, Al, Bh, Bl = 32768 B
#define NSTAGE 3
#define SMEM_TOTAL (1024 + NSTAGE * STAGE2)   // 99328 B (2 CTAs/SM: 194 KB < 228 KB)

// ---------------- device scratch (no allocations anywhere) ----------------
__device__ __nv_bfloat16 g_Wv_hi[EMB * EMB],   g_Wv_lo[EMB * EMB];
__device__ __nv_bfloat16 g_Wo_hi[EMB * EMB],   g_Wo_lo[EMB * EMB];
__device__ __nv_bfloat16 g_Wl_hi[MLM * EMB],   g_Wl_lo[MLM * EMB];
__device__ __nv_bfloat16 g_val_hi[NTOK * EMB], g_val_lo[NTOK * EMB];
__device__ __nv_bfloat16 g_qk_hi[2 * NTOK * EMB], g_qk_lo[2 * NTOK * EMB]; // q | k
__device__ __nv_bfloat16 g_vpT_hi[(long)BATCH * EMB * LSEQ], g_vpT_lo[(long)BATCH * EMB * LSEQ];
__device__ __nv_bfloat16 g_qkl_hi[2 * NTOK * MLM], g_qkl_lo[2 * NTOK * MLM]; // ql | kl (post-softmax)
__device__ float         g_attn[(long)BATCH * LSEQ * LSEQ];
__device__ __nv_bfloat16 g_attn_hi[(long)BATCH * LSEQ * LSEQ], g_attn_lo[(long)BATCH * LSEQ * LSEQ];
__device__ __nv_bfloat16 g_out2_hi[NTOK * EMB], g_out2_lo[NTOK * EMB];

// ---------------- device helpers ----------------
__device__ __forceinline__ uint32_t smem_u32(const void* p) {
    uint32_t a;
    asm("{ .reg .u64 t; cvta.to.shared.u64 t, %1; cvt.u32.u64 %0, t; }" : "=r"(a) : "l"(p));
    return a;
}
__device__ __forceinline__ void ldsm4(uint32_t* r, uint32_t addr) {
    asm volatile("ldmatrix.sync.aligned.m8n8.x4.shared.b16 {%0,%1,%2,%3}, [%4];"
                 : "=r"(r[0]), "=r"(r[1]), "=r"(r[2]), "=r"(r[3]) : "r"(addr));
}
__device__ __forceinline__ void mma_bf16(float* c, const uint32_t* a,
                                         uint32_t b0, uint32_t b1) {
    asm volatile(
        "mma.sync.aligned.m16n8k16.row.col.f32.bf16.bf16.f32 "
        "{%0,%1,%2,%3}, {%4,%5,%6,%7}, {%8,%9}, {%0,%1,%2,%3};"
        : "+f"(c[0]), "+f"(c[1]), "+f"(c[2]), "+f"(c[3])
        : "r"(a[0]), "r"(a[1]), "r"(a[2]), "r"(a[3]), "r"(b0), "r"(b1));
}
__device__ __forceinline__ void mbar_init(uint32_t mb, uint32_t cnt) {
    asm volatile("mbarrier.init.shared.b64 [%0], %1;" :: "r"(mb), "r"(cnt) : "memory");
}
__device__ __forceinline__ void mbar_expect(uint32_t mb, uint32_t bytes) {
    asm volatile("mbarrier.arrive.expect_tx.shared.b64 _, [%0], %1;"
                 :: "r"(mb), "r"(bytes) : "memory");
}
__device__ __forceinline__ void mbar_wait(uint32_t mb, uint32_t parity) {
    asm volatile(
        "{\n\t.reg .pred P;\n"
        "LW%=:\n\tmbarrier.try_wait.parity.acquire.cta.shared::cta.b64 P, [%0], %1, 0x989680;\n\t"
        "@P bra LD%=;\n\tbra LW%=;\nLD%=:\n\t}"
        :: "r"(mb), "r"(parity) : "memory");
}
__device__ __forceinline__ void tma3d(uint32_t dst, const void* tmap,
                                      int x, int y, int z, uint32_t mb) {
    asm volatile(
        "cp.async.bulk.tensor.3d.shared::cta.global.tile.mbarrier::complete_tx::bytes "
        "[%0], [%1, {%2, %3, %4}], [%5];"
        :: "r"(dst), "l"(tmap), "r"(x), "r"(y), "r"(z), "r"(mb) : "memory");
}
__device__ __forceinline__ uint32_t pack_bf(float a, float b) {
    __nv_bfloat16 ha = __float2bfloat16(a), hb = __float2bfloat16(b);
    return (uint32_t)__bfloat16_as_ushort(ha) | ((uint32_t)__bfloat16_as_ushort(hb) << 16);
}
#define SWZ64(o) ((o) ^ (((o) >> 3) & 0x30))

// ---------------------------------------------------------------------------
// bf16-split NT GEMM, TMA-fed triple-buffered, HMMA mma.sync m16n8k16:
//   C[m,n] = sum_k (Ahi+Alo)[m,k]*(Bhi+Blo)[n,k]   (3-term split, fp32 accum)
// All 12 LDSM.x4 per k16-step issued before the 48 MMAs (no LDSM->MMA RAW chain).
// mode 0: fp32 out (+biases). mode 1: bf16 hi/lo split out.
// mode 2: N=64 landmark path — fused softmax over 64 cols (scale 1/8) then hi/lo.
// 128x128 CTA tile, 256 threads = 8 warps (2 x 4), warp tile 64x32.
// ---------------------------------------------------------------------------
__global__ __launch_bounds__(GT, 2)
void gemm_tma_kernel(const __grid_constant__ CUtensorMap tAh,
                     const __grid_constant__ CUtensorMap tAl,
                     const __grid_constant__ CUtensorMap tBh,
                     const __grid_constant__ CUtensorMap tBl,
                     float* __restrict__ Cf,
                     __nv_bfloat16* __restrict__ Chi, __nv_bfloat16* __restrict__ Clo,
                     int M, int N, int K, int zA, int zB, long sC,
                     const float* __restrict__ bias_m, const float* __restrict__ bias_n,
                     int mode)
{
    extern __shared__ __align__(1024) char smem[];

    const int tid  = threadIdx.x;
    const int wid  = tid >> 5;
    const int lane = tid & 31;
    const int wm   = wid >> 2;       // 0..1  (64-row half)
    const int wn   = wid & 3;        // 0..3  (32-col quarter)
    const uint32_t sb = smem_u32(smem);
    const int bz = blockIdx.z;

    if (mode == 0) Cf += (long)bz * sC; else { Chi += (long)bz * sC; Clo += (long)bz * sC; }

    const int m0 = blockIdx.y * TM;
    const int n0 = blockIdx.x * TN;
    const int za = zA ? bz : 0;
    const int zb = zB ? bz : 0;

    if (tid == 0)
        for (int s = 0; s < NSTAGE; s++) mbar_init(sb + s * 8, 1);
    __syncthreads();

    const int nch = K / KC;
    auto issue = [&](int c, int s) {
        uint32_t dst = sb + 1024 + s * STAGE2;
        uint32_t mb  = sb + s * 8;
        mbar_expect(mb, STAGE2);
        int kt = c * KC;
        tma3d(dst,             &tAh, kt, m0, za, mb);
        tma3d(dst + TILE2,     &tAl, kt, m0, za, mb);
        tma3d(dst + 2 * TILE2, &tBh, kt, n0, zb, mb);
        tma3d(dst + 3 * TILE2, &tBl, kt, n0, zb, mb);
    };
    if (tid == 0)
        for (int s = 0; s < NSTAGE && s < nch; s++) issue(s, s);

    float acc[4][4][4];
#pragma unroll
    for (int i = 0; i < 4; i++)
#pragma unroll
        for (int j = 0; j < 4; j++)
#pragma unroll
            for (int r = 0; r < 4; r++) acc[i][j][r] = 0.f;

    // ldmatrix lane addressing: row offset lane&15, k-half byte offset lane>>4
    const int lrow = (lane & 15);
    const int lcol = (lane >> 4) * 16;   // 0 or 16 bytes

    for (int c = 0; c < nch; c++) {
        const int s = c % NSTAGE;
        mbar_wait(sb + s * 8, (c / NSTAGE) & 1);

        const uint32_t sAh = sb + 1024 + s * STAGE2;
        const uint32_t sAl = sAh + TILE2;
        const uint32_t sBh = sAh + 2 * TILE2;
        const uint32_t sBl = sAh + 3 * TILE2;

#pragma unroll
        for (int ks = 0; ks < 2; ks++) {
            const uint32_t kb = ks * 32 + lcol;    // byte offset within 64B row

            // ---- all 12 LDSM.x4 first: no MMA waits on an in-flight LDSM ----
            uint32_t ah[4][4], al[4][4], bh[4][2], bl[4][2];
#pragma unroll
            for (int mi = 0; mi < 4; mi++) {
                uint32_t o = (uint32_t)(wm * 64 + mi * 16 + lrow) * 64 + kb;
                ldsm4(ah[mi], sAh + SWZ64(o));
            }
#pragma unroll
            for (int nb = 0; nb < 2; nb++) {
                uint32_t t[4];
                uint32_t o = (uint32_t)(wn * 32 + nb * 16 + lrow) * 64 + kb;
                ldsm4(t, sBh + SWZ64(o));
                bh[nb * 2 + 0][0] = t[0]; bh[nb * 2 + 0][1] = t[2];
                bh[nb * 2 + 1][0] = t[1]; bh[nb * 2 + 1][1] = t[3];
            }
#pragma unroll
            for (int mi = 0; mi < 4; mi++) {
                uint32_t o = (uint32_t)(wm * 64 + mi * 16 + lrow) * 64 + kb;
                ldsm4(al[mi], sAl + SWZ64(o));
            }
#pragma unroll
            for (int nb = 0; nb < 2; nb++) {
                uint32_t t[4];
                uint32_t o = (uint32_t)(wn * 32 + nb * 16 + lrow) * 64 + kb;
                ldsm4(t, sBl + SWZ64(o));
                bl[nb * 2 + 0][0] = t[0]; bl[nb * 2 + 0][1] = t[2];
                bl[nb * 2 + 1][0] = t[1]; bl[nb * 2 + 1][1] = t[3];
            }

            // ---- 48 MMAs, all operands in registers ----
#pragma unroll
            for (int mi = 0; mi < 4; mi++)
#pragma unroll
                for (int f = 0; f < 4; f++)
                    mma_bf16(acc[mi][f], ah[mi], bh[f][0], bh[f][1]);
#pragma unroll
            for (int mi = 0; mi < 4; mi++)
#pragma unroll
                for (int f = 0; f < 4; f++)
                    mma_bf16(acc[mi][f], al[mi], bh[f][0], bh[f][1]);
#pragma unroll
            for (int mi = 0; mi < 4; mi++)
#pragma unroll
                for (int f = 0; f < 4; f++)
                    mma_bf16(acc[mi][f], ah[mi], bl[f][0], bl[f][1]);
        }
        __syncthreads();   // all warps done reading stage s
        if (tid == 0 && c + NSTAGE < nch) issue(c + NSTAGE, s);
    }

    // ---------------- epilogues ----------------
    if (mode == 2) {
        // Fused softmax over 64 landmark cols. Stage fp32 tile (128 x 64) in smem.
        float* sred = (float*)(smem + 1024);   // [128][65]
#pragma unroll
        for (int mi = 0; mi < 4; mi++)
#pragma unroll
            for (int half = 0; half < 2; half++) {
                int ml = wm * 64 + mi * 16 + half * 8 + (lane >> 2);
#pragma unroll
                for (int f = 0; f < 4; f++) {
                    int n = wn * 32 + f * 8 + (lane & 3) * 2;
                    if (n < 64) {
                        sred[ml * 65 + n]     = acc[mi][f][half * 2 + 0] + bias_n[n];
                        sred[ml * 65 + n + 1] = acc[mi][f][half * 2 + 1] + bias_n[n + 1];
                    }
                }
            }
        __syncthreads();
        // one warp -> 16 rows
        for (int i = 0; i < 16; i++) {
            int r = wid * 16 + i;
            float v0 = sred[r * 65 + lane] * 0.125f;
            float v1 = sred[r * 65 + lane + 32] * 0.125f;
            float mx = fmaxf(v0, v1);
#pragma unroll
            for (int o = 16; o; o >>= 1) mx = fmaxf(mx, __shfl_xor_sync(0xffffffffu, mx, o));
            float e0 = __expf(v0 - mx), e1 = __expf(v1 - mx);
            float sm = e0 + e1;
#pragma unroll
            for (int o = 16; o; o >>= 1) sm += __shfl_xor_sync(0xffffffffu, sm, o);
            float inv = 1.0f / sm;
            float o0 = e0 * inv, o1 = e1 * inv;
            __nv_bfloat16 h0 = __float2bfloat16(o0), h1 = __float2bfloat16(o1);
            long base = (long)(m0 + r) * 64;
            Chi[base + lane]      = h0;
            Chi[base + lane + 32] = h1;
            Clo[base + lane]      = __float2bfloat16(o0 - __bfloat162float(h0));
            Clo[base + lane + 32] = __float2bfloat16(o1 - __bfloat162float(h1));
        }
        return;
    }

    const int rbase = m0 + wm * 64 + (lane >> 2);
    const int cbase = n0 + wn * 32 + (lane & 3) * 2;
#pragma unroll
    for (int mi = 0; mi < 4; mi++) {
#pragma unroll
        for (int half = 0; half < 2; half++) {
            int m = rbase + mi * 16 + half * 8;
            if (m >= M) continue;
            float bm = bias_m ? bias_m[m] : 0.f;
#pragma unroll
            for (int f = 0; f < 4; f++) {
                int n = cbase + f * 8;
                if (n >= N) continue;
                float f0 = acc[mi][f][half * 2 + 0] + bm + (bias_n ? bias_n[n] : 0.f);
                float f1 = acc[mi][f][half * 2 + 1] + bm + (bias_n ? bias_n[n + 1] : 0.f);
                long o = (long)m * N + n;
                if (mode == 0) {
                    *reinterpret_cast<float2*>(Cf + o) = make_float2(f0, f1);
                } else {
                    __nv_bfloat16 h0 = __float2bfloat16(f0), h1 = __float2bfloat16(f1);
                    uint32_t hv = (uint32_t)__bfloat16_as_ushort(h0) |
                                  ((uint32_t)__bfloat16_as_ushort(h1) << 16);
                    uint32_t lv = pack_bf(f0 - __bfloat162float(h0), f1 - __bfloat162float(h1));
                    *reinterpret_cast<uint32_t*>(Chi + o) = hv;
                    *reinterpret_cast<uint32_t*>(Clo + o) = lv;
                }
            }
        }
    }
}

// ---------------------------------------------------------------------------
// Fused fp32 -> bf16 hi/lo split for ALL six operands in one launch.
// ---------------------------------------------------------------------------
#define N4_WV (EMB * EMB / 4)        // 262144 -> 1024 blocks
#define N4_WL (MLM * EMB / 4)        // 16384  -> 64 blocks
#define N4_X  (NTOK * EMB / 4)       // 1048576-> 4096 blocks
#define BL_WV (N4_WV / 256)
#define BL_WL (N4_WL / 256)
#define BL_X  (N4_X / 256)
#define SPLIT_BLOCKS (2 * BL_WV + BL_WL + 3 * BL_X)   // 14400

__global__ __launch_bounds__(256)
void split_all_kernel(const float4* __restrict__ Wv, const float4* __restrict__ Wo,
                      const float4* __restrict__ Wl, const float4* __restrict__ Val,
                      const float4* __restrict__ Q,  const float4* __restrict__ Kk,
                      uint2* __restrict__ WvH, uint2* __restrict__ WvL,
                      uint2* __restrict__ WoH, uint2* __restrict__ WoL,
                      uint2* __restrict__ WlH, uint2* __restrict__ WlL,
                      uint2* __restrict__ VaH, uint2* __restrict__ VaL,
                      uint2* __restrict__ QH,  uint2* __restrict__ QL,
                      uint2* __restrict__ KH,  uint2* __restrict__ KL)
{
    int b = blockIdx.x;
    const float4* src; uint2 *hi, *lo; int loc;
    if      (b < BL_WV)                        { src = Wv;  hi = WvH; lo = WvL; loc = b; }
    else if (b < 2 * BL_WV)                    { src = Wo;  hi = WoH; lo = WoL; loc = b - BL_WV; }
    else if (b < 2 * BL_WV + BL_WL)            { src = Wl;  hi = WlH; lo = WlL; loc = b - 2 * BL_WV; }
    else if (b < 2 * BL_WV + BL_WL + BL_X)     { src = Val; hi = VaH; lo = VaL; loc = b - 2 * BL_WV - BL_WL; }
    else if (b < 2 * BL_WV + BL_WL + 2 * BL_X) { src = Q;   hi = QH;  lo = QL;  loc = b - 2 * BL_WV - BL_WL - BL_X; }
    else                                       { src = Kk;  hi = KH;  lo = KL;  loc = b - 2 * BL_WV - BL_WL - 2 * BL_X; }
    int i = loc * 256 + threadIdx.x;
    float4 v = src[i];
    __nv_bfloat16 h0 = __float2bfloat16(v.x), h1 = __float2bfloat16(v.y);
    __nv_bfloat16 h2 = __float2bfloat16(v.z), h3 = __float2bfloat16(v.w);
    uint2 hv, lv;
    hv.x = (uint32_t)__bfloat16_as_ushort(h0) | ((uint32_t)__bfloat16_as_ushort(h1) << 16);
    hv.y = (uint32_t)__bfloat16_as_ushort(h2) | ((uint32_t)__bfloat16_as_ushort(h3) << 16);
    lv.x = pack_bf(v.x - __bfloat162float(h0), v.y - __bfloat162float(h1));
    lv.y = pack_bf(v.z - __bfloat162float(h2), v.w - __bfloat162float(h3));
    hi[i] = hv;
    lo[i] = lv;
}

// ---------------------------------------------------------------------------
// softmax over 2048 (key dim), scale 1/8; fp32 in, bf16 hi/lo out.
// ---------------------------------------------------------------------------
__global__ __launch_bounds__(256)
void softmax2048_kernel(const float* __restrict__ X, __nv_bfloat16* __restrict__ Hi,
                        __nv_bfloat16* __restrict__ Lo)
{
    const float* p = X + (long)blockIdx.x * 2048;
    int tid = threadIdx.x, lane = tid & 31, wid = tid >> 5;
    __shared__ float red[8];

    float v[8];
    float m = -3.4e38f;
#pragma unroll
    for (int i = 0; i < 8; i++) { v[i] = p[tid + 256 * i] * 0.125f; m = fmaxf(m, v[i]); }
#pragma unroll
    for (int o = 16; o; o >>= 1) m = fmaxf(m, __shfl_xor_sync(0xffffffffu, m, o));
    if (lane == 0) red[wid] = m;
    __syncthreads();
    float mm = red[0];
#pragma unroll
    for (int w = 1; w < 8; w++) mm = fmaxf(mm, red[w]);

    float s = 0.f;
#pragma unroll
    for (int i = 0; i < 8; i++) { v[i] = __expf(v[i] - mm); s += v[i]; }
#pragma unroll
    for (int o = 16; o; o >>= 1) s += __shfl_xor_sync(0xffffffffu, s, o);
    __syncthreads();
    if (lane == 0) red[wid] = s;
    __syncthreads();
    float ss = 0.f;
#pragma unroll
    for (int w = 0; w < 8; w++) ss += red[w];
    float inv = 1.0f / ss;

    long base = (long)blockIdx.x * 2048;
#pragma unroll
    for (int i = 0; i < 8; i++) {
        float f = v[i] * inv;
        __nv_bfloat16 h = __float2bfloat16(f);
        Hi[base + tid + 256 * i] = h;
        Lo[base + tid + 256 * i] = __float2bfloat16(f - __bfloat162float(h));
    }
}

// ---------------------------------------------------------------------------
// Host side
// ---------------------------------------------------------------------------
typedef CUresult (*TmaEncodeFn)(CUtensorMap*, CUtensorMapDataType, cuuint32_t, void*,
                                const cuuint64_t*, const cuuint64_t*,
                                const cuuint32_t*, const cuuint32_t*,
                                CUtensorMapInterleave, CUtensorMapSwizzle,
                                CUtensorMapL2promotion, CUtensorMapFloatOOBfill);

static void enc_tma(TmaEncodeFn fn, CUtensorMap* t, void* base,
                    long K, long rows, long Z, long zStrideElems)
{
    cuuint64_t dims[3] = {(cuuint64_t)K, (cuuint64_t)rows, (cuuint64_t)Z};
    cuuint64_t str[2]  = {(cuuint64_t)(K * 2), (cuuint64_t)(zStrideElems * 2)};
    cuuint32_t box[3]  = {KC, 128, 1};
    cuuint32_t es[3]   = {1, 1, 1};
    fn(t, CU_TENSOR_MAP_DATA_TYPE_UINT16, 3, base, dims, str, box, es,
       CU_TENSOR_MAP_INTERLEAVE_NONE, CU_TENSOR_MAP_SWIZZLE_64B,
       CU_TENSOR_MAP_L2_PROMOTION_L2_128B, CU_TENSOR_MAP_FLOAT_OOB_FILL_NONE);
}

extern "C" void kernel_launch(void* const* d_in, const int* in_sizes, int n_in,
                              void* d_out, int out_size)
{
    const float* query = (const float*)d_in[0];
    const float* key   = (const float*)d_in[1];
    const float* value = (const float*)d_in[2];
    const float* Wv    = (const float*)d_in[3];
    const float* bv    = (const float*)d_in[4];
    const float* Wl    = (const float*)d_in[5];
    const float* bl    = (const float*)d_in[6];
    const float* Wo    = (const float*)d_in[7];
    const float* bo    = (const float*)d_in[8];
    float* out = (float*)d_out;
    (void)in_sizes; (void)n_in; (void)out_size;

    cudaFuncSetAttribute(gemm_tma_kernel,
                         cudaFuncAttributeMaxDynamicSharedMemorySize, SMEM_TOTAL);

    TmaEncodeFn encode = nullptr;
    cudaDriverEntryPointQueryResult qr;
    cudaGetDriverEntryPointByVersion("cuTensorMapEncodeTiled", (void**)&encode,
                                     12000, cudaEnableDefault, &qr);

    __nv_bfloat16 *Wv_hi, *Wv_lo, *Wo_hi, *Wo_lo, *Wl_hi, *Wl_lo;
    __nv_bfloat16 *val_hi, *val_lo, *qk_hi, *qk_lo;
    __nv_bfloat16 *vpT_hi, *vpT_lo, *qkl_hi, *qkl_lo;
    __nv_bfloat16 *attn_hi, *attn_lo, *out2_hi, *out2_lo;
    float *attnf;
    cudaGetSymbolAddress((void**)&Wv_hi,  g_Wv_hi);  cudaGetSymbolAddress((void**)&Wv_lo,  g_Wv_lo);
    cudaGetSymbolAddress((void**)&Wo_hi,  g_Wo_hi);  cudaGetSymbolAddress((void**)&Wo_lo,  g_Wo_lo);
    cudaGetSymbolAddress((void**)&Wl_hi,  g_Wl_hi);  cudaGetSymbolAddress((void**)&Wl_lo,  g_Wl_lo);
    cudaGetSymbolAddress((void**)&val_hi, g_val_hi); cudaGetSymbolAddress((void**)&val_lo, g_val_lo);
    cudaGetSymbolAddress((void**)&qk_hi,  g_qk_hi);  cudaGetSymbolAddress((void**)&qk_lo,  g_qk_lo);
    cudaGetSymbolAddress((void**)&vpT_hi, g_vpT_hi); cudaGetSymbolAddress((void**)&vpT_lo, g_vpT_lo);
    cudaGetSymbolAddress((void**)&qkl_hi, g_qkl_hi); cudaGetSymbolAddress((void**)&qkl_lo, g_qkl_lo);
    cudaGetSymbolAddress((void**)&attn_hi, g_attn_hi); cudaGetSymbolAddress((void**)&attn_lo, g_attn_lo);
    cudaGetSymbolAddress((void**)&out2_hi, g_out2_hi); cudaGetSymbolAddress((void**)&out2_lo, g_out2_lo);
    cudaGetSymbolAddress((void**)&attnf, g_attn);

    dim3 blk(256);

    // 1) fused split of all six fp32 operands -> bf16 hi/lo
    split_all_kernel<<<SPLIT_BLOCKS, blk>>>(
        (const float4*)Wv, (const float4*)Wo, (const float4*)Wl,
        (const float4*)value, (const float4*)query, (const float4*)key,
        (uint2*)Wv_hi, (uint2*)Wv_lo, (uint2*)Wo_hi, (uint2*)Wo_lo,
        (uint2*)Wl_hi, (uint2*)Wl_lo, (uint2*)val_hi, (uint2*)val_lo,
        (uint2*)qk_hi, (uint2*)qk_lo,
        (uint2*)(qk_hi + (long)NTOK * EMB), (uint2*)(qk_lo + (long)NTOK * EMB));

    // --- tensormaps (host-side, capture-time only) ---
    CUtensorMap tWvH, tWvL, tValH, tValL, tQkH, tQkL, tWlH, tWlL;
    CUtensorMap tQlH, tQlL, tKlH, tKlL, tAtH, tAtL, tVpH, tVpL;
    CUtensorMap tO2H, tO2L, tWoH, tWoL;
    enc_tma(encode, &tWvH, Wv_hi, EMB, EMB, 1, (long)EMB * EMB);
    enc_tma(encode, &tWvL, Wv_lo, EMB, EMB, 1, (long)EMB * EMB);
    enc_tma(encode, &tValH, val_hi, EMB, LSEQ, BATCH, (long)LSEQ * EMB);
    enc_tma(encode, &tValL, val_lo, EMB, LSEQ, BATCH, (long)LSEQ * EMB);
    enc_tma(encode, &tQkH, qk_hi, EMB, 2 * NTOK, 1, (long)2 * NTOK * EMB);
    enc_tma(encode, &tQkL, qk_lo, EMB, 2 * NTOK, 1, (long)2 * NTOK * EMB);
    enc_tma(encode, &tWlH, Wl_hi, EMB, MLM, 1, (long)MLM * EMB);
    enc_tma(encode, &tWlL, Wl_lo, EMB, MLM, 1, (long)MLM * EMB);
    enc_tma(encode, &tQlH, qkl_hi, MLM, LSEQ, BATCH, (long)LSEQ * MLM);
    enc_tma(encode, &tQlL, qkl_lo, MLM, LSEQ, BATCH, (long)LSEQ * MLM);
    enc_tma(encode, &tKlH, qkl_hi + (long)NTOK * MLM, MLM, LSEQ, BATCH, (long)LSEQ * MLM);
    enc_tma(encode, &tKlL, qkl_lo + (long)NTOK * MLM, MLM, LSEQ, BATCH, (long)LSEQ * MLM);
    enc_tma(encode, &tAtH, attn_hi, LSEQ, LSEQ, BATCH, (long)LSEQ * LSEQ);
    enc_tma(encode, &tAtL, attn_lo, LSEQ, LSEQ, BATCH, (long)LSEQ * LSEQ);
    enc_tma(encode, &tVpH, vpT_hi, LSEQ, EMB, BATCH, (long)EMB * LSEQ);
    enc_tma(encode, &tVpL, vpT_lo, LSEQ, EMB, BATCH, (long)EMB * LSEQ);
    enc_tma(encode, &tO2H, out2_hi, EMB, NTOK, 1, (long)NTOK * EMB);
    enc_tma(encode, &tO2L, out2_lo, EMB, NTOK, 1, (long)NTOK * EMB);
    enc_tma(encode, &tWoH, Wo_hi, EMB, EMB, 1, (long)EMB * EMB);
    enc_tma(encode, &tWoL, Wo_lo, EMB, EMB, 1, (long)EMB * EMB);

    // 2) VprojT[b,e,k] = Wv x value^T + bv  -> bf16 hi/lo   (A=Wv, B=value[b])
    gemm_tma_kernel<<<dim3(LSEQ / TN, EMB / TM, BATCH), blk, SMEM_TOTAL>>>(
        tWvH, tWvL, tValH, tValL, nullptr, vpT_hi, vpT_lo,
        EMB, LSEQ, EMB, 0, 1, (long)EMB * LSEQ, bv, nullptr, 1);

    // 3) landmark logits (q|k, M=8192, N=64) + fused softmax64 -> qkl hi/lo
    gemm_tma_kernel<<<dim3(1, 2 * NTOK / TM, 1), blk, SMEM_TOTAL>>>(
        tQkH, tQkL, tWlH, tWlL, nullptr, qkl_hi, qkl_lo,
        2 * NTOK, MLM, EMB, 0, 0, 0L, nullptr, bl, 2);

    // 4) scores S[b,q,k] = ql . kl (K=64) -> fp32
    gemm_tma_kernel<<<dim3(LSEQ / TN, LSEQ / TM, BATCH), blk, SMEM_TOTAL>>>(
        tQlH, tQlL, tKlH, tKlL, attnf, nullptr, nullptr,
        LSEQ, LSEQ, MLM, 1, 1, (long)LSEQ * LSEQ, nullptr, nullptr, 0);

    // 5) softmax over keys -> bf16 hi/lo
    softmax2048_kernel<<<NTOK, blk>>>(attnf, attn_hi, attn_lo);

    // 6) out2[b,q,e] = attn x vpT (K=2048) -> bf16 hi/lo
    gemm_tma_kernel<<<dim3(EMB / TN, LSEQ / TM, BATCH), blk, SMEM_TOTAL>>>(
        tAtH, tAtL, tVpH, tVpL, nullptr, out2_hi, out2_lo,
        LSEQ, EMB, LSEQ, 1, 1, (long)LSEQ * EMB, nullptr, nullptr, 1);

    // 7) out = out2 x Wo^T + bo -> fp32 d_out
    gemm_tma_kernel<<<dim3(EMB / TN, NTOK / TM, 1), blk, SMEM_TOTAL>>>(
        tO2H, tO2L, tWoH, tWoL, out, nullptr, nullptr,
        NTOK, EMB, EMB, 0, 0, 0L, nullptr, bo, 0);
}

// round 15
// speedup vs baseline: 1.0042x; 1.0042x over previous
#include <cuda_runtime.h>
#include <cuda.h>
#include <cuda_bf16.h>
#include <stdint.h>

// Problem constants: B=2, L=2048, E=1024, M_LM=64
#define BATCH 2
#define LSEQ  2048
#define EMB   1024
#define MLM   64
#define NTOK  (BATCH * LSEQ)   // 4096

// GEMM tile config
#define TM 128
#define TN 128
#define KC 32                    // bf16 K elems per chunk (64B row, SW64)
#define GT 256                   // threads per GEMM CTA (8 warps)
#define NWARP 8
#define TILE2 8192               // 128 rows x 64 B
#define STAGE2 (4 * TILE2)       // Ah, Al, Bh, Bl = 32768 B
#define NSTAGE 3
#define SMEM_TOTAL (1024 + NSTAGE * STAGE2)   // 99328 B (2 CTAs/SM)

// ---------------- device scratch (no allocations anywhere) ----------------
__device__ __nv_bfloat16 g_Wv_hi[EMB * EMB],   g_Wv_lo[EMB * EMB];
__device__ __nv_bfloat16 g_Wo_hi[EMB * EMB],   g_Wo_lo[EMB * EMB];
__device__ __nv_bfloat16 g_Wl_hi[MLM * EMB],   g_Wl_lo[MLM * EMB];
__device__ __nv_bfloat16 g_val_hi[NTOK * EMB], g_val_lo[NTOK * EMB];
__device__ __nv_bfloat16 g_qk_hi[2 * NTOK * EMB], g_qk_lo[2 * NTOK * EMB]; // q | k
__device__ __nv_bfloat16 g_vpT_hi[(long)BATCH * EMB * LSEQ], g_vpT_lo[(long)BATCH * EMB * LSEQ];
__device__ __nv_bfloat16 g_qkl_hi[2 * NTOK * MLM], g_qkl_lo[2 * NTOK * MLM]; // ql | kl (post-softmax)
__device__ float         g_attn[(long)BATCH * LSEQ * LSEQ];
__device__ __nv_bfloat16 g_attn_hi[(long)BATCH * LSEQ * LSEQ], g_attn_lo[(long)BATCH * LSEQ * LSEQ];
__device__ __nv_bfloat16 g_out2_hi[NTOK * EMB], g_out2_lo[NTOK * EMB];

// ---------------- device helpers ----------------
__device__ __forceinline__ uint32_t smem_u32(const void* p) {
    uint32_t a;
    asm("{ .reg .u64 t; cvta.to.shared.u64 t, %1; cvt.u32.u64 %0, t; }" : "=r"(a) : "l"(p));
    return a;
}
__device__ __forceinline__ void ldsm4(uint32_t* r, uint32_t addr) {
    asm volatile("ldmatrix.sync.aligned.m8n8.x4.shared.b16 {%0,%1,%2,%3}, [%4];"
                 : "=r"(r[0]), "=r"(r[1]), "=r"(r[2]), "=r"(r[3]) : "r"(addr));
}
__device__ __forceinline__ void mma_bf16(float* c, const uint32_t* a,
                                         uint32_t b0, uint32_t b1) {
    asm volatile(
        "mma.sync.aligned.m16n8k16.row.col.f32.bf16.bf16.f32 "
        "{%0,%1,%2,%3}, {%4,%5,%6,%7}, {%8,%9}, {%0,%1,%2,%3};"
        : "+f"(c[0]), "+f"(c[1]), "+f"(c[2]), "+f"(c[3])
        : "r"(a[0]), "r"(a[1]), "r"(a[2]), "r"(a[3]), "r"(b0), "r"(b1));
}
__device__ __forceinline__ void mbar_init(uint32_t mb, uint32_t cnt) {
    asm volatile("mbarrier.init.shared.b64 [%0], %1;" :: "r"(mb), "r"(cnt) : "memory");
}
__device__ __forceinline__ void mbar_expect(uint32_t mb, uint32_t bytes) {
    asm volatile("mbarrier.arrive.expect_tx.shared.b64 _, [%0], %1;"
                 :: "r"(mb), "r"(bytes) : "memory");
}
__device__ __forceinline__ void mbar_arrive(uint32_t mb) {
    asm volatile("mbarrier.arrive.shared.b64 _, [%0];" :: "r"(mb) : "memory");
}
__device__ __forceinline__ void mbar_wait(uint32_t mb, uint32_t parity) {
    asm volatile(
        "{\n\t.reg .pred P;\n"
        "LW%=:\n\tmbarrier.try_wait.parity.acquire.cta.shared::cta.b64 P, [%0], %1, 0x989680;\n\t"
        "@P bra LD%=;\n\tbra LW%=;\nLD%=:\n\t}"
        :: "r"(mb), "r"(parity) : "memory");
}
__device__ __forceinline__ void tma3d(uint32_t dst, const void* tmap,
                                      int x, int y, int z, uint32_t mb) {
    asm volatile(
        "cp.async.bulk.tensor.3d.shared::cta.global.tile.mbarrier::complete_tx::bytes "
        "[%0], [%1, {%2, %3, %4}], [%5];"
        :: "r"(dst), "l"(tmap), "r"(x), "r"(y), "r"(z), "r"(mb) : "memory");
}
__device__ __forceinline__ uint32_t pack_bf(float a, float b) {
    __nv_bfloat16 ha = __float2bfloat16(a), hb = __float2bfloat16(b);
    return (uint32_t)__bfloat16_as_ushort(ha) | ((uint32_t)__bfloat16_as_ushort(hb) << 16);
}
#define SWZ64(o) ((o) ^ (((o) >> 3) & 0x30))

// ---------------------------------------------------------------------------
// bf16-split NT GEMM, TMA-fed 3-stage producer/consumer ring (no per-chunk
// __syncthreads — per-stage empty mbarriers with 8 warp-arrives), HMMA:
//   C[m,n] = sum_k (Ahi+Alo)[m,k]*(Bhi+Blo)[n,k]   (3-term split, fp32 accum)
// mode 0: fp32 out (+biases). mode 1: bf16 hi/lo split out.
// mode 2: N=64 landmark path — fused softmax over 64 cols (scale 1/8) then hi/lo.
// 128x128 CTA tile, 256 threads = 8 warps (2 x 4), warp tile 64x32.
// ---------------------------------------------------------------------------
__global__ __launch_bounds__(GT, 2)
void gemm_tma_kernel(const __grid_constant__ CUtensorMap tAh,
                     const __grid_constant__ CUtensorMap tAl,
                     const __grid_constant__ CUtensorMap tBh,
                     const __grid_constant__ CUtensorMap tBl,
                     float* __restrict__ Cf,
                     __nv_bfloat16* __restrict__ Chi, __nv_bfloat16* __restrict__ Clo,
                     int M, int N, int K, int zA, int zB, long sC,
                     const float* __restrict__ bias_m, const float* __restrict__ bias_n,
                     int mode)
{
    extern __shared__ __align__(1024) char smem[];

    const int tid  = threadIdx.x;
    const int wid  = tid >> 5;
    const int lane = tid & 31;
    const int wm   = wid >> 2;       // 0..1  (64-row half)
    const int wn   = wid & 3;        // 0..3  (32-col quarter)
    const uint32_t sb = smem_u32(smem);
    const int bz = blockIdx.z;

    if (mode == 0) Cf += (long)bz * sC; else { Chi += (long)bz * sC; Clo += (long)bz * sC; }

    const int m0 = blockIdx.y * TM;
    const int n0 = blockIdx.x * TN;
    const int za = zA ? bz : 0;
    const int zb = zB ? bz : 0;

    // full[s] at sb + s*8 (tx-count), empty[s] at sb + 64 + s*8 (8 warp arrives)
    if (tid == 0)
        for (int s = 0; s < NSTAGE; s++) {
            mbar_init(sb + s * 8, 1);
            mbar_init(sb + 64 + s * 8, NWARP);
        }
    __syncthreads();

    const int nch = K / KC;
    auto issue = [&](int c, int s) {
        uint32_t dst = sb + 1024 + s * STAGE2;
        uint32_t mb  = sb + s * 8;
        mbar_expect(mb, STAGE2);
        int kt = c * KC;
        tma3d(dst,             &tAh, kt, m0, za, mb);
        tma3d(dst + TILE2,     &tAl, kt, m0, za, mb);
        tma3d(dst + 2 * TILE2, &tBh, kt, n0, zb, mb);
        tma3d(dst + 3 * TILE2, &tBl, kt, n0, zb, mb);
    };
    const bool producer = (wid == NWARP - 1) && (lane == 0);  // priority warp
    if (producer)
        for (int s = 0; s < NSTAGE && s < nch; s++) issue(s, s);

    float acc[4][4][4];
#pragma unroll
    for (int i = 0; i < 4; i++)
#pragma unroll
        for (int j = 0; j < 4; j++)
#pragma unroll
            for (int r = 0; r < 4; r++) acc[i][j][r] = 0.f;

    // ldmatrix lane addressing: row offset lane&15, k-half byte offset lane>>4
    const int lrow = (lane & 15);
    const int lcol = (lane >> 4) * 16;   // 0 or 16 bytes

    for (int c = 0; c < nch; c++) {
        const int s = c % NSTAGE;
        const int rnd = c / NSTAGE;
        mbar_wait(sb + s * 8, rnd & 1);

        const uint32_t sAh = sb + 1024 + s * STAGE2;
        const uint32_t sAl = sAh + TILE2;
        const uint32_t sBh = sAh + 2 * TILE2;
        const uint32_t sBl = sAh + 3 * TILE2;

#pragma unroll
        for (int ks = 0; ks < 2; ks++) {
            const uint32_t kb = ks * 32 + lcol;    // byte offset within 64B row

            // A_hi fragments: 4 x (16x16)
            uint32_t ah[4][4];
#pragma unroll
            for (int mi = 0; mi < 4; mi++) {
                uint32_t o = (uint32_t)(wm * 64 + mi * 16 + lrow) * 64 + kb;
                ldsm4(ah[mi], sAh + SWZ64(o));
            }

            // B_hi fragments
            uint32_t bh[4][2];
#pragma unroll
            for (int nb = 0; nb < 2; nb++) {
                uint32_t t[4];
                uint32_t o = (uint32_t)(wn * 32 + nb * 16 + lrow) * 64 + kb;
                ldsm4(t, sBh + SWZ64(o));
                bh[nb * 2 + 0][0] = t[0]; bh[nb * 2 + 0][1] = t[2];
                bh[nb * 2 + 1][0] = t[1]; bh[nb * 2 + 1][1] = t[3];
            }

            // hi * hi
#pragma unroll
            for (int mi = 0; mi < 4; mi++)
#pragma unroll
                for (int f = 0; f < 4; f++)
                    mma_bf16(acc[mi][f], ah[mi], bh[f][0], bh[f][1]);

            // lo * hi (stream A_lo)
#pragma unroll
            for (int mi = 0; mi < 4; mi++) {
                uint32_t al[4];
                uint32_t o = (uint32_t)(wm * 64 + mi * 16 + lrow) * 64 + kb;
                ldsm4(al, sAl + SWZ64(o));
#pragma unroll
                for (int f = 0; f < 4; f++)
                    mma_bf16(acc[mi][f], al, bh[f][0], bh[f][1]);
            }

            // hi * lo (stream B_lo)
#pragma unroll
            for (int nb = 0; nb < 2; nb++) {
                uint32_t t[4];
                uint32_t o = (uint32_t)(wn * 32 + nb * 16 + lrow) * 64 + kb;
                ldsm4(t, sBl + SWZ64(o));
#pragma unroll
                for (int mi = 0; mi < 4; mi++) {
                    mma_bf16(acc[mi][nb * 2 + 0], ah[mi], t[0], t[2]);
                    mma_bf16(acc[mi][nb * 2 + 1], ah[mi], t[1], t[3]);
                }
            }
        }

        // this warp done reading stage s
        if (lane == 0) mbar_arrive(sb + 64 + s * 8);
        // producer: refill stage s once all 8 warps have released it
        if (producer) {
            int j = c + NSTAGE;
            if (j < nch) {
                mbar_wait(sb + 64 + s * 8, rnd & 1);   // empty[s] round rnd done
                issue(j, s);
            }
        }
    }
    __syncthreads();   // required before any smem reuse below (mode 2)

    // ---------------- epilogues ----------------
    if (mode == 2) {
        // Fused softmax over 64 landmark cols. Stage fp32 tile (128 x 64) in smem.
        float* sred = (float*)(smem + 1024);   // [128][65]
#pragma unroll
        for (int mi = 0; mi < 4; mi++)
#pragma unroll
            for (int half = 0; half < 2; half++) {
                int ml = wm * 64 + mi * 16 + half * 8 + (lane >> 2);
#pragma unroll
                for (int f = 0; f < 4; f++) {
                    int n = wn * 32 + f * 8 + (lane & 3) * 2;
                    if (n < 64) {
                        sred[ml * 65 + n]     = acc[mi][f][half * 2 + 0] + bias_n[n];
                        sred[ml * 65 + n + 1] = acc[mi][f][half * 2 + 1] + bias_n[n + 1];
                    }
                }
            }
        __syncthreads();
        // one warp -> 16 rows
        for (int i = 0; i < 16; i++) {
            int r = wid * 16 + i;
            float v0 = sred[r * 65 + lane] * 0.125f;
            float v1 = sred[r * 65 + lane + 32] * 0.125f;
            float mx = fmaxf(v0, v1);
#pragma unroll
            for (int o = 16; o; o >>= 1) mx = fmaxf(mx, __shfl_xor_sync(0xffffffffu, mx, o));
            float e0 = __expf(v0 - mx), e1 = __expf(v1 - mx);
            float sm = e0 + e1;
#pragma unroll
            for (int o = 16; o; o >>= 1) sm += __shfl_xor_sync(0xffffffffu, sm, o);
            float inv = 1.0f / sm;
            float o0 = e0 * inv, o1 = e1 * inv;
            __nv_bfloat16 h0 = __float2bfloat16(o0), h1 = __float2bfloat16(o1);
            long base = (long)(m0 + r) * 64;
            Chi[base + lane]      = h0;
            Chi[base + lane + 32] = h1;
            Clo[base + lane]      = __float2bfloat16(o0 - __bfloat162float(h0));
            Clo[base + lane + 32] = __float2bfloat16(o1 - __bfloat162float(h1));
        }
        return;
    }

    const int rbase = m0 + wm * 64 + (lane >> 2);
    const int cbase = n0 + wn * 32 + (lane & 3) * 2;
#pragma unroll
    for (int mi = 0; mi < 4; mi++) {
#pragma unroll
        for (int half = 0; half < 2; half++) {
            int m = rbase + mi * 16 + half * 8;
            if (m >= M) continue;
            float bm = bias_m ? bias_m[m] : 0.f;
#pragma unroll
            for (int f = 0; f < 4; f++) {
                int n = cbase + f * 8;
                if (n >= N) continue;
                float f0 = acc[mi][f][half * 2 + 0] + bm + (bias_n ? bias_n[n] : 0.f);
                float f1 = acc[mi][f][half * 2 + 1] + bm + (bias_n ? bias_n[n + 1] : 0.f);
                long o = (long)m * N + n;
                if (mode == 0) {
                    *reinterpret_cast<float2*>(Cf + o) = make_float2(f0, f1);
                } else {
                    __nv_bfloat16 h0 = __float2bfloat16(f0), h1 = __float2bfloat16(f1);
                    uint32_t hv = (uint32_t)__bfloat16_as_ushort(h0) |
                                  ((uint32_t)__bfloat16_as_ushort(h1) << 16);
                    uint32_t lv = pack_bf(f0 - __bfloat162float(h0), f1 - __bfloat162float(h1));
                    *reinterpret_cast<uint32_t*>(Chi + o) = hv;
                    *reinterpret_cast<uint32_t*>(Clo + o) = lv;
                }
            }
        }
    }
}

// ---------------------------------------------------------------------------
// Fused fp32 -> bf16 hi/lo split for ALL six operands in one launch.
// ---------------------------------------------------------------------------
#define N4_WV (EMB * EMB / 4)
#define N4_WL (MLM * EMB / 4)
#define N4_X  (NTOK * EMB / 4)
#define BL_WV (N4_WV / 256)
#define BL_WL (N4_WL / 256)
#define BL_X  (N4_X / 256)
#define SPLIT_BLOCKS (2 * BL_WV + BL_WL + 3 * BL_X)

__global__ __launch_bounds__(256)
void split_all_kernel(const float4* __restrict__ Wv, const float4* __restrict__ Wo,
                      const float4* __restrict__ Wl, const float4* __restrict__ Val,
                      const float4* __restrict__ Q,  const float4* __restrict__ Kk,
                      uint2* __restrict__ WvH, uint2* __restrict__ WvL,
                      uint2* __restrict__ WoH, uint2* __restrict__ WoL,
                      uint2* __restrict__ WlH, uint2* __restrict__ WlL,
                      uint2* __restrict__ VaH, uint2* __restrict__ VaL,
                      uint2* __restrict__ QH,  uint2* __restrict__ QL,
                      uint2* __restrict__ KH,  uint2* __restrict__ KL)
{
    int b = blockIdx.x;
    const float4* src; uint2 *hi, *lo; int loc;
    if      (b < BL_WV)                        { src = Wv;  hi = WvH; lo = WvL; loc = b; }
    else if (b < 2 * BL_WV)                    { src = Wo;  hi = WoH; lo = WoL; loc = b - BL_WV; }
    else if (b < 2 * BL_WV + BL_WL)            { src = Wl;  hi = WlH; lo = WlL; loc = b - 2 * BL_WV; }
    else if (b < 2 * BL_WV + BL_WL + BL_X)     { src = Val; hi = VaH; lo = VaL; loc = b - 2 * BL_WV - BL_WL; }
    else if (b < 2 * BL_WV + BL_WL + 2 * BL_X) { src = Q;   hi = QH;  lo = QL;  loc = b - 2 * BL_WV - BL_WL - BL_X; }
    else                                       { src = Kk;  hi = KH;  lo = KL;  loc = b - 2 * BL_WV - BL_WL - 2 * BL_X; }
    int i = loc * 256 + threadIdx.x;
    float4 v = src[i];
    __nv_bfloat16 h0 = __float2bfloat16(v.x), h1 = __float2bfloat16(v.y);
    __nv_bfloat16 h2 = __float2bfloat16(v.z), h3 = __float2bfloat16(v.w);
    uint2 hv, lv;
    hv.x = (uint32_t)__bfloat16_as_ushort(h0) | ((uint32_t)__bfloat16_as_ushort(h1) << 16);
    hv.y = (uint32_t)__bfloat16_as_ushort(h2) | ((uint32_t)__bfloat16_as_ushort(h3) << 16);
    lv.x = pack_bf(v.x - __bfloat162float(h0), v.y - __bfloat162float(h1));
    lv.y = pack_bf(v.z - __bfloat162float(h2), v.w - __bfloat162float(h3));
    hi[i] = hv;
    lo[i] = lv;
}

// ---------------------------------------------------------------------------
// softmax over 2048 (key dim), scale 1/8; fp32 in, bf16 hi/lo out.
// ---------------------------------------------------------------------------
__global__ __launch_bounds__(256)
void softmax2048_kernel(const float* __restrict__ X, __nv_bfloat16* __restrict__ Hi,
                        __nv_bfloat16* __restrict__ Lo)
{
    const float* p = X + (long)blockIdx.x * 2048;
    int tid = threadIdx.x, lane = tid & 31, wid = tid >> 5;
    __shared__ float red[8];

    float v[8];
    float m = -3.4e38f;
#pragma unroll
    for (int i = 0; i < 8; i++) { v[i] = p[tid + 256 * i] * 0.125f; m = fmaxf(m, v[i]); }
#pragma unroll
    for (int o = 16; o; o >>= 1) m = fmaxf(m, __shfl_xor_sync(0xffffffffu, m, o));
    if (lane == 0) red[wid] = m;
    __syncthreads();
    float mm = red[0];
#pragma unroll
    for (int w = 1; w < 8; w++) mm = fmaxf(mm, red[w]);

    float s = 0.f;
#pragma unroll
    for (int i = 0; i < 8; i++) { v[i] = __expf(v[i] - mm); s += v[i]; }
#pragma unroll
    for (int o = 16; o; o >>= 1) s += __shfl_xor_sync(0xffffffffu, s, o);
    __syncthreads();
    if (lane == 0) red[wid] = s;
    __syncthreads();
    float ss = 0.f;
#pragma unroll
    for (int w = 0; w < 8; w++) ss += red[w];
    float inv = 1.0f / ss;

    long base = (long)blockIdx.x * 2048;
#pragma unroll
    for (int i = 0; i < 8; i++) {
        float f = v[i] * inv;
        __nv_bfloat16 h = __float2bfloat16(f);
        Hi[base + tid + 256 * i] = h;
        Lo[base + tid + 256 * i] = __float2bfloat16(f - __bfloat162float(h));
    }
}

// ---------------------------------------------------------------------------
// Host side
// ---------------------------------------------------------------------------
typedef CUresult (*TmaEncodeFn)(CUtensorMap*, CUtensorMapDataType, cuuint32_t, void*,
                                const cuuint64_t*, const cuuint64_t*,
                                const cuuint32_t*, const cuuint32_t*,
                                CUtensorMapInterleave, CUtensorMapSwizzle,
                                CUtensorMapL2promotion, CUtensorMapFloatOOBfill);

static void enc_tma(TmaEncodeFn fn, CUtensorMap* t, void* base,
                    long K, long rows, long Z, long zStrideElems)
{
    cuuint64_t dims[3] = {(cuuint64_t)K, (cuuint64_t)rows, (cuuint64_t)Z};
    cuuint64_t str[2]  = {(cuuint64_t)(K * 2), (cuuint64_t)(zStrideElems * 2)};
    cuuint32_t box[3]  = {KC, 128, 1};
    cuuint32_t es[3]   = {1, 1, 1};
    fn(t, CU_TENSOR_MAP_DATA_TYPE_UINT16, 3, base, dims, str, box, es,
       CU_TENSOR_MAP_INTERLEAVE_NONE, CU_TENSOR_MAP_SWIZZLE_64B,
       CU_TENSOR_MAP_L2_PROMOTION_L2_128B, CU_TENSOR_MAP_FLOAT_OOB_FILL_NONE);
}

extern "C" void kernel_launch(void* const* d_in, const int* in_sizes, int n_in,
                              void* d_out, int out_size)
{
    const float* query = (const float*)d_in[0];
    const float* key   = (const float*)d_in[1];
    const float* value = (const float*)d_in[2];
    const float* Wv    = (const float*)d_in[3];
    const float* bv    = (const float*)d_in[4];
    const float* Wl    = (const float*)d_in[5];
    const float* bl    = (const float*)d_in[6];
    const float* Wo    = (const float*)d_in[7];
    const float* bo    = (const float*)d_in[8];
    float* out = (float*)d_out;
    (void)in_sizes; (void)n_in; (void)out_size;

    cudaFuncSetAttribute(gemm_tma_kernel,
                         cudaFuncAttributeMaxDynamicSharedMemorySize, SMEM_TOTAL);

    TmaEncodeFn encode = nullptr;
    cudaDriverEntryPointQueryResult qr;
    cudaGetDriverEntryPointByVersion("cuTensorMapEncodeTiled", (void**)&encode,
                                     12000, cudaEnableDefault, &qr);

    __nv_bfloat16 *Wv_hi, *Wv_lo, *Wo_hi, *Wo_lo, *Wl_hi, *Wl_lo;
    __nv_bfloat16 *val_hi, *val_lo, *qk_hi, *qk_lo;
    __nv_bfloat16 *vpT_hi, *vpT_lo, *qkl_hi, *qkl_lo;
    __nv_bfloat16 *attn_hi, *attn_lo, *out2_hi, *out2_lo;
    float *attnf;
    cudaGetSymbolAddress((void**)&Wv_hi,  g_Wv_hi);  cudaGetSymbolAddress((void**)&Wv_lo,  g_Wv_lo);
    cudaGetSymbolAddress((void**)&Wo_hi,  g_Wo_hi);  cudaGetSymbolAddress((void**)&Wo_lo,  g_Wo_lo);
    cudaGetSymbolAddress((void**)&Wl_hi,  g_Wl_hi);  cudaGetSymbolAddress((void**)&Wl_lo,  g_Wl_lo);
    cudaGetSymbolAddress((void**)&val_hi, g_val_hi); cudaGetSymbolAddress((void**)&val_lo, g_val_lo);
    cudaGetSymbolAddress((void**)&qk_hi,  g_qk_hi);  cudaGetSymbolAddress((void**)&qk_lo,  g_qk_lo);
    cudaGetSymbolAddress((void**)&vpT_hi, g_vpT_hi); cudaGetSymbolAddress((void**)&vpT_lo, g_vpT_lo);
    cudaGetSymbolAddress((void**)&qkl_hi, g_qkl_hi); cudaGetSymbolAddress((void**)&qkl_lo, g_qkl_lo);
    cudaGetSymbolAddress((void**)&attn_hi, g_attn_hi); cudaGetSymbolAddress((void**)&attn_lo, g_attn_lo);
    cudaGetSymbolAddress((void**)&out2_hi, g_out2_hi); cudaGetSymbolAddress((void**)&out2_lo, g_out2_lo);
    cudaGetSymbolAddress((void**)&attnf, g_attn);

    dim3 blk(256);

    // 1) fused split of all six fp32 operands -> bf16 hi/lo
    split_all_kernel<<<SPLIT_BLOCKS, blk>>>(
        (const float4*)Wv, (const float4*)Wo, (const float4*)Wl,
        (const float4*)value, (const float4*)query, (const float4*)key,
        (uint2*)Wv_hi, (uint2*)Wv_lo, (uint2*)Wo_hi, (uint2*)Wo_lo,
        (uint2*)Wl_hi, (uint2*)Wl_lo, (uint2*)val_hi, (uint2*)val_lo,
        (uint2*)qk_hi, (uint2*)qk_lo,
        (uint2*)(qk_hi + (long)NTOK * EMB), (uint2*)(qk_lo + (long)NTOK * EMB));

    // --- tensormaps (host-side, capture-time only) ---
    CUtensorMap tWvH, tWvL, tValH, tValL, tQkH, tQkL, tWlH, tWlL;
    CUtensorMap tQlH, tQlL, tKlH, tKlL, tAtH, tAtL, tVpH, tVpL;
    CUtensorMap tO2H, tO2L, tWoH, tWoL;
    enc_tma(encode, &tWvH, Wv_hi, EMB, EMB, 1, (long)EMB * EMB);
    enc_tma(encode, &tWvL, Wv_lo, EMB, EMB, 1, (long)EMB * EMB);
    enc_tma(encode, &tValH, val_hi, EMB, LSEQ, BATCH, (long)LSEQ * EMB);
    enc_tma(encode, &tValL, val_lo, EMB, LSEQ, BATCH, (long)LSEQ * EMB);
    enc_tma(encode, &tQkH, qk_hi, EMB, 2 * NTOK, 1, (long)2 * NTOK * EMB);
    enc_tma(encode, &tQkL, qk_lo, EMB, 2 * NTOK, 1, (long)2 * NTOK * EMB);
    enc_tma(encode, &tWlH, Wl_hi, EMB, MLM, 1, (long)MLM * EMB);
    enc_tma(encode, &tWlL, Wl_lo, EMB, MLM, 1, (long)MLM * EMB);
    enc_tma(encode, &tQlH, qkl_hi, MLM, LSEQ, BATCH, (long)LSEQ * MLM);
    enc_tma(encode, &tQlL, qkl_lo, MLM, LSEQ, BATCH, (long)LSEQ * MLM);
    enc_tma(encode, &tKlH, qkl_hi + (long)NTOK * MLM, MLM, LSEQ, BATCH, (long)LSEQ * MLM);
    enc_tma(encode, &tKlL, qkl_lo + (long)NTOK * MLM, MLM, LSEQ, BATCH, (long)LSEQ * MLM);
    enc_tma(encode, &tAtH, attn_hi, LSEQ, LSEQ, BATCH, (long)LSEQ * LSEQ);
    enc_tma(encode, &tAtL, attn_lo, LSEQ, LSEQ, BATCH, (long)LSEQ * LSEQ);
    enc_tma(encode, &tVpH, vpT_hi, LSEQ, EMB, BATCH, (long)EMB * LSEQ);
    enc_tma(encode, &tVpL, vpT_lo, LSEQ, EMB, BATCH, (long)EMB * LSEQ);
    enc_tma(encode, &tO2H, out2_hi, EMB, NTOK, 1, (long)NTOK * EMB);
    enc_tma(encode, &tO2L, out2_lo, EMB, NTOK, 1, (long)NTOK * EMB);
    enc_tma(encode, &tWoH, Wo_hi, EMB, EMB, 1, (long)EMB * EMB);
    enc_tma(encode, &tWoL, Wo_lo, EMB, EMB, 1, (long)EMB * EMB);

    // 2) VprojT[b,e,k] = Wv x value^T + bv  -> bf16 hi/lo
    gemm_tma_kernel<<<dim3(LSEQ / TN, EMB / TM, BATCH), blk, SMEM_TOTAL>>>(
        tWvH, tWvL, tValH, tValL, nullptr, vpT_hi, vpT_lo,
        EMB, LSEQ, EMB, 0, 1, (long)EMB * LSEQ, bv, nullptr, 1);

    // 3) landmark logits (q|k, M=8192, N=64) + fused softmax64 -> qkl hi/lo
    gemm_tma_kernel<<<dim3(1, 2 * NTOK / TM, 1), blk, SMEM_TOTAL>>>(
        tQkH, tQkL, tWlH, tWlL, nullptr, qkl_hi, qkl_lo,
        2 * NTOK, MLM, EMB, 0, 0, 0L, nullptr, bl, 2);

    // 4) scores S[b,q,k] = ql . kl (K=64) -> fp32
    gemm_tma_kernel<<<dim3(LSEQ / TN, LSEQ / TM, BATCH), blk, SMEM_TOTAL>>>(
        tQlH, tQlL, tKlH, tKlL, attnf, nullptr, nullptr,
        LSEQ, LSEQ, MLM, 1, 1, (long)LSEQ * LSEQ, nullptr, nullptr, 0);

    // 5) softmax over keys -> bf16 hi/lo
    softmax2048_kernel<<<NTOK, blk>>>(attnf, attn_hi, attn_lo);

    // 6) out2[b,q,e] = attn x vpT (K=2048) -> bf16 hi/lo
    gemm_tma_kernel<<<dim3(EMB / TN, LSEQ / TM, BATCH), blk, SMEM_TOTAL>>>(
        tAtH, tAtL, tVpH, tVpL, nullptr, out2_hi, out2_lo,
        LSEQ, EMB, LSEQ, 1, 1, (long)LSEQ * EMB, nullptr, nullptr, 1);

    // 7) out = out2 x Wo^T + bo -> fp32 d_out
    gemm_tma_kernel<<<dim3(EMB / TN, NTOK / TM, 1), blk, SMEM_TOTAL>>>(
        tO2H, tO2L, tWoH, tWoL, out, nullptr, nullptr,
        NTOK, EMB, EMB, 0, 0, 0L, nullptr, bo, 0);
}

// round 16
// speedup vs baseline: 1.4324x; 1.4264x over previous
#include <cuda_runtime.h>
#include <cuda.h>
#include <cuda_fp16.h>
#include <stdint.h>

// Problem constants: B=2, L=2048, E=1024, M_LM=64
#define BATCH 2
#define LSEQ  2048
#define EMB   1024
#define MLM   64
#define NTOK  (BATCH * LSEQ)   // 4096

// GEMM tile config
#define TM 128
#define TN 128
#define KC 32                    // fp16 K elems per chunk (64B row, SW64)
#define GT 256                   // threads per GEMM CTA
#define TILE2 8192               // 128 rows x 64 B
#define STAGE2 (4 * TILE2)       // fixed layout: Ah, Al, Bh, Bl slots
#define NSTAGE 3
#define SMEM_TOTAL (1024 + NSTAGE * STAGE2)   // 99328 B (2 CTAs/SM)

// ---------------- device scratch (no allocations anywhere) ----------------
__device__ __half g_Wv_hi[EMB * EMB], g_Wv_lo[EMB * EMB];
__device__ __half g_Wo_hi[EMB * EMB];
__device__ __half g_Wl_hi[MLM * EMB];
__device__ __half g_val_hi[NTOK * EMB];
__device__ __half g_qk_hi[2 * NTOK * EMB];                    // q | k
__device__ __half g_vpT_hi[(long)BATCH * EMB * LSEQ];
__device__ __half g_qkl_hi[2 * NTOK * MLM];                   // ql | kl (post-softmax)
__device__ float  g_attn[(long)BATCH * LSEQ * LSEQ];
__device__ __half g_attn_hi[(long)BATCH * LSEQ * LSEQ], g_attn_lo[(long)BATCH * LSEQ * LSEQ];
__device__ __half g_out2_hi[NTOK * EMB], g_out2_lo[NTOK * EMB];

// ---------------- device helpers ----------------
__device__ __forceinline__ uint32_t smem_u32(const void* p) {
    uint32_t a;
    asm("{ .reg .u64 t; cvta.to.shared.u64 t, %1; cvt.u32.u64 %0, t; }" : "=r"(a) : "l"(p));
    return a;
}
__device__ __forceinline__ void ldsm4(uint32_t* r, uint32_t addr) {
    asm volatile("ldmatrix.sync.aligned.m8n8.x4.shared.b16 {%0,%1,%2,%3}, [%4];"
                 : "=r"(r[0]), "=r"(r[1]), "=r"(r[2]), "=r"(r[3]) : "r"(addr));
}
__device__ __forceinline__ void mma_f16(float* c, const uint32_t* a,
                                        uint32_t b0, uint32_t b1) {
    asm volatile(
        "mma.sync.aligned.m16n8k16.row.col.f32.f16.f16.f32 "
        "{%0,%1,%2,%3}, {%4,%5,%6,%7}, {%8,%9}, {%0,%1,%2,%3};"
        : "+f"(c[0]), "+f"(c[1]), "+f"(c[2]), "+f"(c[3])
        : "r"(a[0]), "r"(a[1]), "r"(a[2]), "r"(a[3]), "r"(b0), "r"(b1));
}
__device__ __forceinline__ void mbar_init(uint32_t mb, uint32_t cnt) {
    asm volatile("mbarrier.init.shared.b64 [%0], %1;" :: "r"(mb), "r"(cnt) : "memory");
}
__device__ __forceinline__ void mbar_expect(uint32_t mb, uint32_t bytes) {
    asm volatile("mbarrier.arrive.expect_tx.shared.b64 _, [%0], %1;"
                 :: "r"(mb), "r"(bytes) : "memory");
}
__device__ __forceinline__ void mbar_wait(uint32_t mb, uint32_t parity) {
    asm volatile(
        "{\n\t.reg .pred P;\n"
        "LW%=:\n\tmbarrier.try_wait.parity.acquire.cta.shared::cta.b64 P, [%0], %1, 0x989680;\n\t"
        "@P bra LD%=;\n\tbra LW%=;\nLD%=:\n\t}"
        :: "r"(mb), "r"(parity) : "memory");
}
__device__ __forceinline__ void tma3d(uint32_t dst, const void* tmap,
                                      int x, int y, int z, uint32_t mb) {
    asm volatile(
        "cp.async.bulk.tensor.3d.shared::cta.global.tile.mbarrier::complete_tx::bytes "
        "[%0], [%1, {%2, %3, %4}], [%5];"
        :: "r"(dst), "l"(tmap), "r"(x), "r"(y), "r"(z), "r"(mb) : "memory");
}
__device__ __forceinline__ uint32_t pack_h(float a, float b) {
    __half2 h = __floats2half2_rn(a, b);
    return *reinterpret_cast<uint32_t*>(&h);
}
#define SWZ64(o) ((o) ^ (((o) >> 3) & 0x30))

// ---------------------------------------------------------------------------
// fp16-split NT GEMM, TMA-fed triple-buffered, HMMA mma.sync m16n8k16:
//   NTERMS=1: C = Ahi*Bhi
//   NTERMS=2: C = (Ahi+Alo)*Bhi
//   NTERMS=3: C = (Ahi+Alo)*Bhi + Ahi*Blo
// fp32 accum. Unused lo tiles are never TMA'd or read.
// mode 0: fp32 out (+biases). mode 1: fp16 hi out (+lo if Clo != null).
// mode 2: N=64 landmark path — fused softmax over 64 cols (scale 1/8), hi out.
// 128x128 CTA tile, 256 threads = 8 warps (2 x 4), warp tile 64x32.
// ---------------------------------------------------------------------------
template<int NTERMS>
__global__ __launch_bounds__(GT, 2)
void gemm_tma_kernel(const __grid_constant__ CUtensorMap tAh,
                     const __grid_constant__ CUtensorMap tAl,
                     const __grid_constant__ CUtensorMap tBh,
                     const __grid_constant__ CUtensorMap tBl,
                     float* __restrict__ Cf,
                     __half* __restrict__ Chi, __half* __restrict__ Clo,
                     int M, int N, int K, int zA, int zB, long sC,
                     const float* __restrict__ bias_m, const float* __restrict__ bias_n,
                     int mode)
{
    extern __shared__ __align__(1024) char smem[];

    const int tid  = threadIdx.x;
    const int wid  = tid >> 5;
    const int lane = tid & 31;
    const int wm   = wid >> 2;       // 0..1  (64-row half)
    const int wn   = wid & 3;        // 0..3  (32-col quarter)
    const uint32_t sb = smem_u32(smem);
    const int bz = blockIdx.z;

    if (mode == 0) Cf += (long)bz * sC;
    else { Chi += (long)bz * sC; if (Clo) Clo += (long)bz * sC; }

    const int m0 = blockIdx.y * TM;
    const int n0 = blockIdx.x * TN;
    const int za = zA ? bz : 0;
    const int zb = zB ? bz : 0;

    if (tid == 0)
        for (int s = 0; s < NSTAGE; s++) mbar_init(sb + s * 8, 1);
    __syncthreads();

    const int nch = K / KC;
    auto issue = [&](int c, int s) {
        uint32_t dst = sb + 1024 + s * STAGE2;
        uint32_t mb  = sb + s * 8;
        mbar_expect(mb, (NTERMS + 1) * TILE2);
        int kt = c * KC;
        tma3d(dst,             &tAh, kt, m0, za, mb);
        tma3d(dst + 2 * TILE2, &tBh, kt, n0, zb, mb);
        if constexpr (NTERMS >= 2) tma3d(dst + TILE2,     &tAl, kt, m0, za, mb);
        if constexpr (NTERMS >= 3) tma3d(dst + 3 * TILE2, &tBl, kt, n0, zb, mb);
    };
    if (tid == 0)
        for (int s = 0; s < NSTAGE && s < nch; s++) issue(s, s);

    float acc[4][4][4];
#pragma unroll
    for (int i = 0; i < 4; i++)
#pragma unroll
        for (int j = 0; j < 4; j++)
#pragma unroll
            for (int r = 0; r < 4; r++) acc[i][j][r] = 0.f;

    // ldmatrix lane addressing: row offset lane&15, k-half byte offset lane>>4
    const int lrow = (lane & 15);
    const int lcol = (lane >> 4) * 16;   // 0 or 16 bytes

    for (int c = 0; c < nch; c++) {
        const int s = c % NSTAGE;
        mbar_wait(sb + s * 8, (c / NSTAGE) & 1);

        const uint32_t sAh = sb + 1024 + s * STAGE2;
        const uint32_t sAl = sAh + TILE2;
        const uint32_t sBh = sAh + 2 * TILE2;
        const uint32_t sBl = sAh + 3 * TILE2;

#pragma unroll
        for (int ks = 0; ks < 2; ks++) {
            const uint32_t kb = ks * 32 + lcol;    // byte offset within 64B row

            // A_hi fragments: 4 x (16x16)
            uint32_t ah[4][4];
#pragma unroll
            for (int mi = 0; mi < 4; mi++) {
                uint32_t o = (uint32_t)(wm * 64 + mi * 16 + lrow) * 64 + kb;
                ldsm4(ah[mi], sAh + SWZ64(o));
            }

            // B_hi fragments
            uint32_t bh[4][2];
#pragma unroll
            for (int nb = 0; nb < 2; nb++) {
                uint32_t t[4];
                uint32_t o = (uint32_t)(wn * 32 + nb * 16 + lrow) * 64 + kb;
                ldsm4(t, sBh + SWZ64(o));
                bh[nb * 2 + 0][0] = t[0]; bh[nb * 2 + 0][1] = t[2];
                bh[nb * 2 + 1][0] = t[1]; bh[nb * 2 + 1][1] = t[3];
            }

            // hi * hi
#pragma unroll
            for (int mi = 0; mi < 4; mi++)
#pragma unroll
                for (int f = 0; f < 4; f++)
                    mma_f16(acc[mi][f], ah[mi], bh[f][0], bh[f][1]);

            // lo * hi (stream A_lo)
            if constexpr (NTERMS >= 2) {
#pragma unroll
                for (int mi = 0; mi < 4; mi++) {
                    uint32_t al[4];
                    uint32_t o = (uint32_t)(wm * 64 + mi * 16 + lrow) * 64 + kb;
                    ldsm4(al, sAl + SWZ64(o));
#pragma unroll
                    for (int f = 0; f < 4; f++)
                        mma_f16(acc[mi][f], al, bh[f][0], bh[f][1]);
                }
            }

            // hi * lo (stream B_lo)
            if constexpr (NTERMS >= 3) {
#pragma unroll
                for (int nb = 0; nb < 2; nb++) {
                    uint32_t t[4];
                    uint32_t o = (uint32_t)(wn * 32 + nb * 16 + lrow) * 64 + kb;
                    ldsm4(t, sBl + SWZ64(o));
#pragma unroll
                    for (int mi = 0; mi < 4; mi++) {
                        mma_f16(acc[mi][nb * 2 + 0], ah[mi], t[0], t[2]);
                        mma_f16(acc[mi][nb * 2 + 1], ah[mi], t[1], t[3]);
                    }
                }
            }
        }
        __syncthreads();   // all warps done reading stage s
        if (tid == 0 && c + NSTAGE < nch) issue(c + NSTAGE, s);
    }

    // ---------------- epilogues ----------------
    if (mode == 2) {
        // Fused softmax over 64 landmark cols. Stage fp32 tile (128 x 64) in smem.
        float* sred = (float*)(smem + 1024);   // [128][65]
#pragma unroll
        for (int mi = 0; mi < 4; mi++)
#pragma unroll
            for (int half_ = 0; half_ < 2; half_++) {
                int ml = wm * 64 + mi * 16 + half_ * 8 + (lane >> 2);
#pragma unroll
                for (int f = 0; f < 4; f++) {
                    int n = wn * 32 + f * 8 + (lane & 3) * 2;
                    if (n < 64) {
                        sred[ml * 65 + n]     = acc[mi][f][half_ * 2 + 0] + bias_n[n];
                        sred[ml * 65 + n + 1] = acc[mi][f][half_ * 2 + 1] + bias_n[n + 1];
                    }
                }
            }
        __syncthreads();
        // one warp -> 16 rows
        for (int i = 0; i < 16; i++) {
            int r = wid * 16 + i;
            float v0 = sred[r * 65 + lane] * 0.125f;
            float v1 = sred[r * 65 + lane + 32] * 0.125f;
            float mx = fmaxf(v0, v1);
#pragma unroll
            for (int o = 16; o; o >>= 1) mx = fmaxf(mx, __shfl_xor_sync(0xffffffffu, mx, o));
            float e0 = __expf(v0 - mx), e1 = __expf(v1 - mx);
            float sm = e0 + e1;
#pragma unroll
            for (int o = 16; o; o >>= 1) sm += __shfl_xor_sync(0xffffffffu, sm, o);
            float inv = 1.0f / sm;
            long base = (long)(m0 + r) * 64;
            Chi[base + lane]      = __float2half(e0 * inv);
            Chi[base + lane + 32] = __float2half(e1 * inv);
        }
        return;
    }

    const int rbase = m0 + wm * 64 + (lane >> 2);
    const int cbase = n0 + wn * 32 + (lane & 3) * 2;
#pragma unroll
    for (int mi = 0; mi < 4; mi++) {
#pragma unroll
        for (int half_ = 0; half_ < 2; half_++) {
            int m = rbase + mi * 16 + half_ * 8;
            if (m >= M) continue;
            float bm = bias_m ? bias_m[m] : 0.f;
#pragma unroll
            for (int f = 0; f < 4; f++) {
                int n = cbase + f * 8;
                if (n >= N) continue;
                float f0 = acc[mi][f][half_ * 2 + 0] + bm + (bias_n ? bias_n[n] : 0.f);
                float f1 = acc[mi][f][half_ * 2 + 1] + bm + (bias_n ? bias_n[n + 1] : 0.f);
                long o = (long)m * N + n;
                if (mode == 0) {
                    *reinterpret_cast<float2*>(Cf + o) = make_float2(f0, f1);
                } else {
                    __half h0 = __float2half(f0), h1 = __float2half(f1);
                    *reinterpret_cast<uint32_t*>(Chi + o) = pack_h(f0, f1) ;
                    if (Clo) {
                        float l0 = f0 - __half2float(h0), l1 = f1 - __half2float(h1);
                        *reinterpret_cast<uint32_t*>(Clo + o) = pack_h(l0, l1);
                    }
                }
            }
        }
    }
}

// ---------------------------------------------------------------------------
// Fused fp32 -> fp16 split for all six operands (lo only for Wv).
// ---------------------------------------------------------------------------
#define N4_WV (EMB * EMB / 4)
#define N4_WL (MLM * EMB / 4)
#define N4_X  (NTOK * EMB / 4)
#define BL_WV (N4_WV / 256)
#define BL_WL (N4_WL / 256)
#define BL_X  (N4_X / 256)
#define SPLIT_BLOCKS (2 * BL_WV + BL_WL + 3 * BL_X)

__global__ __launch_bounds__(256)
void split_all_kernel(const float4* __restrict__ Wv, const float4* __restrict__ Wo,
                      const float4* __restrict__ Wl, const float4* __restrict__ Val,
                      const float4* __restrict__ Q,  const float4* __restrict__ Kk,
                      uint2* __restrict__ WvH, uint2* __restrict__ WvL,
                      uint2* __restrict__ WoH, uint2* __restrict__ WlH,
                      uint2* __restrict__ VaH, uint2* __restrict__ QH,
                      uint2* __restrict__ KH)
{
    int b = blockIdx.x;
    const float4* src; uint2 *hi, *lo = nullptr; int loc;
    if      (b < BL_WV)                        { src = Wv;  hi = WvH; lo = WvL; loc = b; }
    else if (b < 2 * BL_WV)                    { src = Wo;  hi = WoH; loc = b - BL_WV; }
    else if (b < 2 * BL_WV + BL_WL)            { src = Wl;  hi = WlH; loc = b - 2 * BL_WV; }
    else if (b < 2 * BL_WV + BL_WL + BL_X)     { src = Val; hi = VaH; loc = b - 2 * BL_WV - BL_WL; }
    else if (b < 2 * BL_WV + BL_WL + 2 * BL_X) { src = Q;   hi = QH;  loc = b - 2 * BL_WV - BL_WL - BL_X; }
    else                                       { src = Kk;  hi = KH;  loc = b - 2 * BL_WV - BL_WL - 2 * BL_X; }
    int i = loc * 256 + threadIdx.x;
    float4 v = src[i];
    __half h0 = __float2half(v.x), h1 = __float2half(v.y);
    __half h2 = __float2half(v.z), h3 = __float2half(v.w);
    uint2 hv;
    hv.x = pack_h(v.x, v.y);
    hv.y = pack_h(v.z, v.w);
    hi[i] = hv;
    if (lo) {
        uint2 lv;
        lv.x = pack_h(v.x - __half2float(h0), v.y - __half2float(h1));
        lv.y = pack_h(v.z - __half2float(h2), v.w - __half2float(h3));
        lo[i] = lv;
    }
}

// ---------------------------------------------------------------------------
// softmax over 2048 (key dim), scale 1/8; fp32 in, fp16 hi/lo out.
// ---------------------------------------------------------------------------
__global__ __launch_bounds__(256)
void softmax2048_kernel(const float* __restrict__ X, __half* __restrict__ Hi,
                        __half* __restrict__ Lo)
{
    const float* p = X + (long)blockIdx.x * 2048;
    int tid = threadIdx.x, lane = tid & 31, wid = tid >> 5;
    __shared__ float red[8];

    float v[8];
    float m = -3.4e38f;
#pragma unroll
    for (int i = 0; i < 8; i++) { v[i] = p[tid + 256 * i] * 0.125f; m = fmaxf(m, v[i]); }
#pragma unroll
    for (int o = 16; o; o >>= 1) m = fmaxf(m, __shfl_xor_sync(0xffffffffu, m, o));
    if (lane == 0) red[wid] = m;
    __syncthreads();
    float mm = red[0];
#pragma unroll
    for (int w = 1; w < 8; w++) mm = fmaxf(mm, red[w]);

    float s = 0.f;
#pragma unroll
    for (int i = 0; i < 8; i++) { v[i] = __expf(v[i] - mm); s += v[i]; }
#pragma unroll
    for (int o = 16; o; o >>= 1) s += __shfl_xor_sync(0xffffffffu, s, o);
    __syncthreads();
    if (lane == 0) red[wid] = s;
    __syncthreads();
    float ss = 0.f;
#pragma unroll
    for (int w = 0; w < 8; w++) ss += red[w];
    float inv = 1.0f / ss;

    long base = (long)blockIdx.x * 2048;
#pragma unroll
    for (int i = 0; i < 8; i++) {
        float f = v[i] * inv;
        __half h = __float2half(f);
        Hi[base + tid + 256 * i] = h;
        Lo[base + tid + 256 * i] = __float2half(f - __half2float(h));
    }
}

// ---------------------------------------------------------------------------
// Host side
// ---------------------------------------------------------------------------
typedef CUresult (*TmaEncodeFn)(CUtensorMap*, CUtensorMapDataType, cuuint32_t, void*,
                                const cuuint64_t*, const cuuint64_t*,
                                const cuuint32_t*, const cuuint32_t*,
                                CUtensorMapInterleave, CUtensorMapSwizzle,
                                CUtensorMapL2promotion, CUtensorMapFloatOOBfill);

static void enc_tma(TmaEncodeFn fn, CUtensorMap* t, void* base,
                    long K, long rows, long Z, long zStrideElems)
{
    cuuint64_t dims[3] = {(cuuint64_t)K, (cuuint64_t)rows, (cuuint64_t)Z};
    cuuint64_t str[2]  = {(cuuint64_t)(K * 2), (cuuint64_t)(zStrideElems * 2)};
    cuuint32_t box[3]  = {KC, 128, 1};
    cuuint32_t es[3]   = {1, 1, 1};
    fn(t, CU_TENSOR_MAP_DATA_TYPE_UINT16, 3, base, dims, str, box, es,
       CU_TENSOR_MAP_INTERLEAVE_NONE, CU_TENSOR_MAP_SWIZZLE_64B,
       CU_TENSOR_MAP_L2_PROMOTION_L2_128B, CU_TENSOR_MAP_FLOAT_OOB_FILL_NONE);
}

extern "C" void kernel_launch(void* const* d_in, const int* in_sizes, int n_in,
                              void* d_out, int out_size)
{
    const float* query = (const float*)d_in[0];
    const float* key   = (const float*)d_in[1];
    const float* value = (const float*)d_in[2];
    const float* Wv    = (const float*)d_in[3];
    const float* bv    = (const float*)d_in[4];
    const float* Wl    = (const float*)d_in[5];
    const float* bl    = (const float*)d_in[6];
    const float* Wo    = (const float*)d_in[7];
    const float* bo    = (const float*)d_in[8];
    float* out = (float*)d_out;
    (void)in_sizes; (void)n_in; (void)out_size;

    cudaFuncSetAttribute(gemm_tma_kernel<1>,
                         cudaFuncAttributeMaxDynamicSharedMemorySize, SMEM_TOTAL);
    cudaFuncSetAttribute(gemm_tma_kernel<2>,
                         cudaFuncAttributeMaxDynamicSharedMemorySize, SMEM_TOTAL);

    TmaEncodeFn encode = nullptr;
    cudaDriverEntryPointQueryResult qr;
    cudaGetDriverEntryPointByVersion("cuTensorMapEncodeTiled", (void**)&encode,
                                     12000, cudaEnableDefault, &qr);

    __half *Wv_hi, *Wv_lo, *Wo_hi, *Wl_hi, *val_hi, *qk_hi;
    __half *vpT_hi, *qkl_hi, *attn_hi, *attn_lo, *out2_hi, *out2_lo;
    float *attnf;
    cudaGetSymbolAddress((void**)&Wv_hi,  g_Wv_hi);  cudaGetSymbolAddress((void**)&Wv_lo, g_Wv_lo);
    cudaGetSymbolAddress((void**)&Wo_hi,  g_Wo_hi);
    cudaGetSymbolAddress((void**)&Wl_hi,  g_Wl_hi);
    cudaGetSymbolAddress((void**)&val_hi, g_val_hi);
    cudaGetSymbolAddress((void**)&qk_hi,  g_qk_hi);
    cudaGetSymbolAddress((void**)&vpT_hi, g_vpT_hi);
    cudaGetSymbolAddress((void**)&qkl_hi, g_qkl_hi);
    cudaGetSymbolAddress((void**)&attn_hi, g_attn_hi); cudaGetSymbolAddress((void**)&attn_lo, g_attn_lo);
    cudaGetSymbolAddress((void**)&out2_hi, g_out2_hi); cudaGetSymbolAddress((void**)&out2_lo, g_out2_lo);
    cudaGetSymbolAddress((void**)&attnf, g_attn);

    dim3 blk(256);

    // 1) fused split: hi for all six operands, lo only for Wv
    split_all_kernel<<<SPLIT_BLOCKS, blk>>>(
        (const float4*)Wv, (const float4*)Wo, (const float4*)Wl,
        (const float4*)value, (const float4*)query, (const float4*)key,
        (uint2*)Wv_hi, (uint2*)Wv_lo, (uint2*)Wo_hi, (uint2*)Wl_hi,
        (uint2*)val_hi, (uint2*)qk_hi, (uint2*)(qk_hi + (long)NTOK * EMB));

    // --- tensormaps (host-side, capture-time only) ---
    CUtensorMap tWvH, tWvL, tValH, tQkH, tWlH;
    CUtensorMap tQlH, tKlH, tAtH, tAtL, tVpH, tO2H, tO2L, tWoH;
    enc_tma(encode, &tWvH, Wv_hi, EMB, EMB, 1, (long)EMB * EMB);
    enc_tma(encode, &tWvL, Wv_lo, EMB, EMB, 1, (long)EMB * EMB);
    enc_tma(encode, &tValH, val_hi, EMB, LSEQ, BATCH, (long)LSEQ * EMB);
    enc_tma(encode, &tQkH, qk_hi, EMB, 2 * NTOK, 1, (long)2 * NTOK * EMB);
    enc_tma(encode, &tWlH, Wl_hi, EMB, MLM, 1, (long)MLM * EMB);
    enc_tma(encode, &tQlH, qkl_hi, MLM, LSEQ, BATCH, (long)LSEQ * MLM);
    enc_tma(encode, &tKlH, qkl_hi + (long)NTOK * MLM, MLM, LSEQ, BATCH, (long)LSEQ * MLM);
    enc_tma(encode, &tAtH, attn_hi, LSEQ, LSEQ, BATCH, (long)LSEQ * LSEQ);
    enc_tma(encode, &tAtL, attn_lo, LSEQ, LSEQ, BATCH, (long)LSEQ * LSEQ);
    enc_tma(encode, &tVpH, vpT_hi, LSEQ, EMB, BATCH, (long)EMB * LSEQ);
    enc_tma(encode, &tO2H, out2_hi, EMB, NTOK, 1, (long)NTOK * EMB);
    enc_tma(encode, &tO2L, out2_lo, EMB, NTOK, 1, (long)NTOK * EMB);
    enc_tma(encode, &tWoH, Wo_hi, EMB, EMB, 1, (long)EMB * EMB);

    // 2) VprojT = (Wv_hi + Wv_lo) x value_hi^T + bv  -> fp16 hi only
    gemm_tma_kernel<2><<<dim3(LSEQ / TN, EMB / TM, BATCH), blk, SMEM_TOTAL>>>(
        tWvH, tWvL, tValH, tValH, nullptr, vpT_hi, nullptr,
        EMB, LSEQ, EMB, 0, 1, (long)EMB * LSEQ, bv, nullptr, 1);

    // 3) landmark logits (q|k, M=8192, N=64), 1-term + fused softmax64 -> qkl hi
    gemm_tma_kernel<1><<<dim3(1, 2 * NTOK / TM, 1), blk, SMEM_TOTAL>>>(
        tQkH, tQkH, tWlH, tWlH, nullptr, qkl_hi, nullptr,
        2 * NTOK, MLM, EMB, 0, 0, 0L, nullptr, bl, 2);

    // 4) scores S = ql_hi . kl_hi (K=64), 1-term -> fp32
    gemm_tma_kernel<1><<<dim3(LSEQ / TN, LSEQ / TM, BATCH), blk, SMEM_TOTAL>>>(
        tQlH, tQlH, tKlH, tKlH, attnf, nullptr, nullptr,
        LSEQ, LSEQ, MLM, 1, 1, (long)LSEQ * LSEQ, nullptr, nullptr, 0);

    // 5) softmax over keys -> fp16 hi/lo (attn must stay split: cancellation amp)
    softmax2048_kernel<<<NTOK, blk>>>(attnf, attn_hi, attn_lo);

    // 6) out2 = (attn_hi + attn_lo) x vpT_hi (K=2048) -> fp16 hi/lo
    gemm_tma_kernel<2><<<dim3(EMB / TN, LSEQ / TM, BATCH), blk, SMEM_TOTAL>>>(
        tAtH, tAtL, tVpH, tVpH, nullptr, out2_hi, out2_lo,
        LSEQ, EMB, LSEQ, 1, 1, (long)LSEQ * EMB, nullptr, nullptr, 1);

    // 7) out = (out2_hi + out2_lo) x Wo_hi^T + bo -> fp32 d_out
    gemm_tma_kernel<2><<<dim3(EMB / TN, NTOK / TM, 1), blk, SMEM_TOTAL>>>(
        tO2H, tO2L, tWoH, tWoH, out, nullptr, nullptr,
        NTOK, EMB, EMB, 0, 0, 0L, nullptr, bo, 0);
}

// round 17
// speedup vs baseline: 1.7448x; 1.2181x over previous
#include <cuda_runtime.h>
#include <cuda.h>
#include <cuda_fp16.h>
#include <stdint.h>

// Problem constants: B=2, L=2048, E=1024, M_LM=64
#define BATCH 2
#define LSEQ  2048
#define EMB   1024
#define MLM   64
#define NTOK  (BATCH * LSEQ)   // 4096

// GEMM tile config
#define TM 128
#define TN 128
#define KC 32                    // fp16 K elems per chunk (64B row, SW64)
#define GT 256                   // threads per GEMM CTA
#define TILE2 8192               // 128 rows x 64 B
#define STAGE2 (4 * TILE2)       // fixed layout: Ah, Al, Bh, Bl slots
#define NSTAGE 3
#define SMEM_TOTAL (1024 + NSTAGE * STAGE2)   // 99328 B (2 CTAs/SM)

// ---------------- device scratch (no allocations anywhere) ----------------
__device__ __half g_Wv_hi[EMB * EMB], g_Wv_lo[EMB * EMB];
__device__ __half g_Wo_hi[EMB * EMB];
__device__ __half g_Wl_hi[MLM * EMB];
__device__ __half g_val_hi[NTOK * EMB];
__device__ __half g_qk_hi[2 * NTOK * EMB];                    // q | k
__device__ __half g_vpT_hi[(long)BATCH * EMB * LSEQ];
__device__ __half g_qkl_hi[2 * NTOK * MLM];                   // ql | kl (post-softmax)
__device__ float  g_attn[(long)BATCH * LSEQ * LSEQ];
__device__ __half g_attn_hi[(long)BATCH * LSEQ * LSEQ];
__device__ __half g_out2_hi[NTOK * EMB], g_out2_lo[NTOK * EMB];

// ---------------- device helpers ----------------
__device__ __forceinline__ uint32_t smem_u32(const void* p) {
    uint32_t a;
    asm("{ .reg .u64 t; cvta.to.shared.u64 t, %1; cvt.u32.u64 %0, t; }" : "=r"(a) : "l"(p));
    return a;
}
__device__ __forceinline__ void ldsm4(uint32_t* r, uint32_t addr) {
    asm volatile("ldmatrix.sync.aligned.m8n8.x4.shared.b16 {%0,%1,%2,%3}, [%4];"
                 : "=r"(r[0]), "=r"(r[1]), "=r"(r[2]), "=r"(r[3]) : "r"(addr));
}
__device__ __forceinline__ void mma_f16(float* c, const uint32_t* a,
                                        uint32_t b0, uint32_t b1) {
    asm volatile(
        "mma.sync.aligned.m16n8k16.row.col.f32.f16.f16.f32 "
        "{%0,%1,%2,%3}, {%4,%5,%6,%7}, {%8,%9}, {%0,%1,%2,%3};"
        : "+f"(c[0]), "+f"(c[1]), "+f"(c[2]), "+f"(c[3])
        : "r"(a[0]), "r"(a[1]), "r"(a[2]), "r"(a[3]), "r"(b0), "r"(b1));
}
__device__ __forceinline__ void mbar_init(uint32_t mb, uint32_t cnt) {
    asm volatile("mbarrier.init.shared.b64 [%0], %1;" :: "r"(mb), "r"(cnt) : "memory");
}
__device__ __forceinline__ void mbar_expect(uint32_t mb, uint32_t bytes) {
    asm volatile("mbarrier.arrive.expect_tx.shared.b64 _, [%0], %1;"
                 :: "r"(mb), "r"(bytes) : "memory");
}
__device__ __forceinline__ void mbar_wait(uint32_t mb, uint32_t parity) {
    asm volatile(
        "{\n\t.reg .pred P;\n"
        "LW%=:\n\tmbarrier.try_wait.parity.acquire.cta.shared::cta.b64 P, [%0], %1, 0x989680;\n\t"
        "@P bra LD%=;\n\tbra LW%=;\nLD%=:\n\t}"
        :: "r"(mb), "r"(parity) : "memory");
}
__device__ __forceinline__ void tma3d(uint32_t dst, const void* tmap,
                                      int x, int y, int z, uint32_t mb) {
    asm volatile(
        "cp.async.bulk.tensor.3d.shared::cta.global.tile.mbarrier::complete_tx::bytes "
        "[%0], [%1, {%2, %3, %4}], [%5];"
        :: "r"(dst), "l"(tmap), "r"(x), "r"(y), "r"(z), "r"(mb) : "memory");
}
__device__ __forceinline__ uint32_t pack_h(float a, float b) {
    __half2 h = __floats2half2_rn(a, b);
    return *reinterpret_cast<uint32_t*>(&h);
}
#define SWZ64(o) ((o) ^ (((o) >> 3) & 0x30))

// ---------------------------------------------------------------------------
// fp16-split NT GEMM, TMA-fed triple-buffered, HMMA mma.sync m16n8k16:
//   NTERMS=1: C = Ahi*Bhi
//   NTERMS=2: C = (Ahi+Alo)*Bhi
// fp32 accum. Unused lo tiles are never TMA'd or read.
// mode 0: fp32 out (+biases). mode 1: fp16 hi out (+lo if Clo != null).
// mode 2: N=64 landmark path — fused softmax over 64 cols (scale 1/8), hi out.
// 128x128 CTA tile, 256 threads = 8 warps (2 x 4), warp tile 64x32.
// ---------------------------------------------------------------------------
template<int NTERMS>
__global__ __launch_bounds__(GT, 2)
void gemm_tma_kernel(const __grid_constant__ CUtensorMap tAh,
                     const __grid_constant__ CUtensorMap tAl,
                     const __grid_constant__ CUtensorMap tBh,
                     const __grid_constant__ CUtensorMap tBl,
                     float* __restrict__ Cf,
                     __half* __restrict__ Chi, __half* __restrict__ Clo,
                     int M, int N, int K, int zA, int zB, long sC,
                     const float* __restrict__ bias_m, const float* __restrict__ bias_n,
                     int mode)
{
    extern __shared__ __align__(1024) char smem[];

    const int tid  = threadIdx.x;
    const int wid  = tid >> 5;
    const int lane = tid & 31;
    const int wm   = wid >> 2;       // 0..1  (64-row half)
    const int wn   = wid & 3;        // 0..3  (32-col quarter)
    const uint32_t sb = smem_u32(smem);
    const int bz = blockIdx.z;

    if (mode == 0) Cf += (long)bz * sC;
    else { Chi += (long)bz * sC; if (Clo) Clo += (long)bz * sC; }

    const int m0 = blockIdx.y * TM;
    const int n0 = blockIdx.x * TN;
    const int za = zA ? bz : 0;
    const int zb = zB ? bz : 0;

    if (tid == 0)
        for (int s = 0; s < NSTAGE; s++) mbar_init(sb + s * 8, 1);
    __syncthreads();

    const int nch = K / KC;
    auto issue = [&](int c, int s) {
        uint32_t dst = sb + 1024 + s * STAGE2;
        uint32_t mb  = sb + s * 8;
        mbar_expect(mb, (NTERMS + 1) * TILE2);
        int kt = c * KC;
        tma3d(dst,             &tAh, kt, m0, za, mb);
        tma3d(dst + 2 * TILE2, &tBh, kt, n0, zb, mb);
        if constexpr (NTERMS >= 2) tma3d(dst + TILE2, &tAl, kt, m0, za, mb);
    };
    if (tid == 0)
        for (int s = 0; s < NSTAGE && s < nch; s++) issue(s, s);

    float acc[4][4][4];
#pragma unroll
    for (int i = 0; i < 4; i++)
#pragma unroll
        for (int j = 0; j < 4; j++)
#pragma unroll
            for (int r = 0; r < 4; r++) acc[i][j][r] = 0.f;

    // ldmatrix lane addressing: row offset lane&15, k-half byte offset lane>>4
    const int lrow = (lane & 15);
    const int lcol = (lane >> 4) * 16;   // 0 or 16 bytes

    for (int c = 0; c < nch; c++) {
        const int s = c % NSTAGE;
        mbar_wait(sb + s * 8, (c / NSTAGE) & 1);

        const uint32_t sAh = sb + 1024 + s * STAGE2;
        const uint32_t sAl = sAh + TILE2;
        const uint32_t sBh = sAh + 2 * TILE2;

#pragma unroll
        for (int ks = 0; ks < 2; ks++) {
            const uint32_t kb = ks * 32 + lcol;    // byte offset within 64B row

            // A_hi fragments: 4 x (16x16)
            uint32_t ah[4][4];
#pragma unroll
            for (int mi = 0; mi < 4; mi++) {
                uint32_t o = (uint32_t)(wm * 64 + mi * 16 + lrow) * 64 + kb;
                ldsm4(ah[mi], sAh + SWZ64(o));
            }

            // B_hi fragments
            uint32_t bh[4][2];
#pragma unroll
            for (int nb = 0; nb < 2; nb++) {
                uint32_t t[4];
                uint32_t o = (uint32_t)(wn * 32 + nb * 16 + lrow) * 64 + kb;
                ldsm4(t, sBh + SWZ64(o));
                bh[nb * 2 + 0][0] = t[0]; bh[nb * 2 + 0][1] = t[2];
                bh[nb * 2 + 1][0] = t[1]; bh[nb * 2 + 1][1] = t[3];
            }

            // hi * hi
#pragma unroll
            for (int mi = 0; mi < 4; mi++)
#pragma unroll
                for (int f = 0; f < 4; f++)
                    mma_f16(acc[mi][f], ah[mi], bh[f][0], bh[f][1]);

            // lo * hi (stream A_lo)
            if constexpr (NTERMS >= 2) {
#pragma unroll
                for (int mi = 0; mi < 4; mi++) {
                    uint32_t al[4];
                    uint32_t o = (uint32_t)(wm * 64 + mi * 16 + lrow) * 64 + kb;
                    ldsm4(al, sAl + SWZ64(o));
#pragma unroll
                    for (int f = 0; f < 4; f++)
                        mma_f16(acc[mi][f], al, bh[f][0], bh[f][1]);
                }
            }
        }
        __syncthreads();   // all warps done reading stage s
        if (tid == 0 && c + NSTAGE < nch) issue(c + NSTAGE, s);
    }

    // ---------------- epilogues ----------------
    if (mode == 2) {
        // Fused softmax over 64 landmark cols. Stage fp32 tile (128 x 64) in smem.
        float* sred = (float*)(smem + 1024);   // [128][65]
#pragma unroll
        for (int mi = 0; mi < 4; mi++)
#pragma unroll
            for (int half_ = 0; half_ < 2; half_++) {
                int ml = wm * 64 + mi * 16 + half_ * 8 + (lane >> 2);
#pragma unroll
                for (int f = 0; f < 4; f++) {
                    int n = wn * 32 + f * 8 + (lane & 3) * 2;
                    if (n < 64) {
                        sred[ml * 65 + n]     = acc[mi][f][half_ * 2 + 0] + bias_n[n];
                        sred[ml * 65 + n + 1] = acc[mi][f][half_ * 2 + 1] + bias_n[n + 1];
                    }
                }
            }
        __syncthreads();
        // one warp -> 16 rows
        for (int i = 0; i < 16; i++) {
            int r = wid * 16 + i;
            float v0 = sred[r * 65 + lane] * 0.125f;
            float v1 = sred[r * 65 + lane + 32] * 0.125f;
            float mx = fmaxf(v0, v1);
#pragma unroll
            for (int o = 16; o; o >>= 1) mx = fmaxf(mx, __shfl_xor_sync(0xffffffffu, mx, o));
            float e0 = __expf(v0 - mx), e1 = __expf(v1 - mx);
            float sm = e0 + e1;
#pragma unroll
            for (int o = 16; o; o >>= 1) sm += __shfl_xor_sync(0xffffffffu, sm, o);
            float inv = 1.0f / sm;
            long base = (long)(m0 + r) * 64;
            Chi[base + lane]      = __float2half(e0 * inv);
            Chi[base + lane + 32] = __float2half(e1 * inv);
        }
        return;
    }

    const int rbase = m0 + wm * 64 + (lane >> 2);
    const int cbase = n0 + wn * 32 + (lane & 3) * 2;
#pragma unroll
    for (int mi = 0; mi < 4; mi++) {
#pragma unroll
        for (int half_ = 0; half_ < 2; half_++) {
            int m = rbase + mi * 16 + half_ * 8;
            if (m >= M) continue;
            float bm = bias_m ? bias_m[m] : 0.f;
#pragma unroll
            for (int f = 0; f < 4; f++) {
                int n = cbase + f * 8;
                if (n >= N) continue;
                float f0 = acc[mi][f][half_ * 2 + 0] + bm + (bias_n ? bias_n[n] : 0.f);
                float f1 = acc[mi][f][half_ * 2 + 1] + bm + (bias_n ? bias_n[n + 1] : 0.f);
                long o = (long)m * N + n;
                if (mode == 0) {
                    *reinterpret_cast<float2*>(Cf + o) = make_float2(f0, f1);
                } else {
                    __half h0 = __float2half(f0), h1 = __float2half(f1);
                    *reinterpret_cast<uint32_t*>(Chi + o) = pack_h(f0, f1);
                    if (Clo) {
                        float l0 = f0 - __half2float(h0), l1 = f1 - __half2float(h1);
                        *reinterpret_cast<uint32_t*>(Clo + o) = pack_h(l0, l1);
                    }
                }
            }
        }
    }
}

// ---------------------------------------------------------------------------
// Fused fp32 -> fp16 split for all six operands (lo only for Wv).
// ---------------------------------------------------------------------------
#define N4_WV (EMB * EMB / 4)
#define N4_WL (MLM * EMB / 4)
#define N4_X  (NTOK * EMB / 4)
#define BL_WV (N4_WV / 256)
#define BL_WL (N4_WL / 256)
#define BL_X  (N4_X / 256)
#define SPLIT_BLOCKS (2 * BL_WV + BL_WL + 3 * BL_X)

__global__ __launch_bounds__(256)
void split_all_kernel(const float4* __restrict__ Wv, const float4* __restrict__ Wo,
                      const float4* __restrict__ Wl, const float4* __restrict__ Val,
                      const float4* __restrict__ Q,  const float4* __restrict__ Kk,
                      uint2* __restrict__ WvH, uint2* __restrict__ WvL,
                      uint2* __restrict__ WoH, uint2* __restrict__ WlH,
                      uint2* __restrict__ VaH, uint2* __restrict__ QH,
                      uint2* __restrict__ KH)
{
    int b = blockIdx.x;
    const float4* src; uint2 *hi, *lo = nullptr; int loc;
    if      (b < BL_WV)                        { src = Wv;  hi = WvH; lo = WvL; loc = b; }
    else if (b < 2 * BL_WV)                    { src = Wo;  hi = WoH; loc = b - BL_WV; }
    else if (b < 2 * BL_WV + BL_WL)            { src = Wl;  hi = WlH; loc = b - 2 * BL_WV; }
    else if (b < 2 * BL_WV + BL_WL + BL_X)     { src = Val; hi = VaH; loc = b - 2 * BL_WV - BL_WL; }
    else if (b < 2 * BL_WV + BL_WL + 2 * BL_X) { src = Q;   hi = QH;  loc = b - 2 * BL_WV - BL_WL - BL_X; }
    else                                       { src = Kk;  hi = KH;  loc = b - 2 * BL_WV - BL_WL - 2 * BL_X; }
    int i = loc * 256 + threadIdx.x;
    float4 v = src[i];
    __half h0 = __float2half(v.x), h1 = __float2half(v.y);
    __half h2 = __float2half(v.z), h3 = __float2half(v.w);
    uint2 hv;
    hv.x = pack_h(v.x, v.y);
    hv.y = pack_h(v.z, v.w);
    hi[i] = hv;
    if (lo) {
        uint2 lv;
        lv.x = pack_h(v.x - __half2float(h0), v.y - __half2float(h1));
        lv.y = pack_h(v.z - __half2float(h2), v.w - __half2float(h3));
        lo[i] = lv;
    }
}

// ---------------------------------------------------------------------------
// softmax over 2048 (key dim), scale 1/8; fp32 in, fp16 hi out.
// (attn is non-negative — single fp16 term is within error budget, amp ~1)
// ---------------------------------------------------------------------------
__global__ __launch_bounds__(256)
void softmax2048_kernel(const float* __restrict__ X, __half* __restrict__ Hi)
{
    const float* p = X + (long)blockIdx.x * 2048;
    int tid = threadIdx.x, lane = tid & 31, wid = tid >> 5;
    __shared__ float red[8];

    float v[8];
    float m = -3.4e38f;
#pragma unroll
    for (int i = 0; i < 8; i++) { v[i] = p[tid + 256 * i] * 0.125f; m = fmaxf(m, v[i]); }
#pragma unroll
    for (int o = 16; o; o >>= 1) m = fmaxf(m, __shfl_xor_sync(0xffffffffu, m, o));
    if (lane == 0) red[wid] = m;
    __syncthreads();
    float mm = red[0];
#pragma unroll
    for (int w = 1; w < 8; w++) mm = fmaxf(mm, red[w]);

    float s = 0.f;
#pragma unroll
    for (int i = 0; i < 8; i++) { v[i] = __expf(v[i] - mm); s += v[i]; }
#pragma unroll
    for (int o = 16; o; o >>= 1) s += __shfl_xor_sync(0xffffffffu, s, o);
    __syncthreads();
    if (lane == 0) red[wid] = s;
    __syncthreads();
    float ss = 0.f;
#pragma unroll
    for (int w = 0; w < 8; w++) ss += red[w];
    float inv = 1.0f / ss;

    long base = (long)blockIdx.x * 2048;
#pragma unroll
    for (int i = 0; i < 8; i++)
        Hi[base + tid + 256 * i] = __float2half(v[i] * inv);
}

// ---------------------------------------------------------------------------
// Host side
// ---------------------------------------------------------------------------
typedef CUresult (*TmaEncodeFn)(CUtensorMap*, CUtensorMapDataType, cuuint32_t, void*,
                                const cuuint64_t*, const cuuint64_t*,
                                const cuuint32_t*, const cuuint32_t*,
                                CUtensorMapInterleave, CUtensorMapSwizzle,
                                CUtensorMapL2promotion, CUtensorMapFloatOOBfill);

static void enc_tma(TmaEncodeFn fn, CUtensorMap* t, void* base,
                    long K, long rows, long Z, long zStrideElems)
{
    cuuint64_t dims[3] = {(cuuint64_t)K, (cuuint64_t)rows, (cuuint64_t)Z};
    cuuint64_t str[2]  = {(cuuint64_t)(K * 2), (cuuint64_t)(zStrideElems * 2)};
    cuuint32_t box[3]  = {KC, 128, 1};
    cuuint32_t es[3]   = {1, 1, 1};
    fn(t, CU_TENSOR_MAP_DATA_TYPE_UINT16, 3, base, dims, str, box, es,
       CU_TENSOR_MAP_INTERLEAVE_NONE, CU_TENSOR_MAP_SWIZZLE_64B,
       CU_TENSOR_MAP_L2_PROMOTION_L2_128B, CU_TENSOR_MAP_FLOAT_OOB_FILL_NONE);
}

extern "C" void kernel_launch(void* const* d_in, const int* in_sizes, int n_in,
                              void* d_out, int out_size)
{
    const float* query = (const float*)d_in[0];
    const float* key   = (const float*)d_in[1];
    const float* value = (const float*)d_in[2];
    const float* Wv    = (const float*)d_in[3];
    const float* bv    = (const float*)d_in[4];
    const float* Wl    = (const float*)d_in[5];
    const float* bl    = (const float*)d_in[6];
    const float* Wo    = (const float*)d_in[7];
    const float* bo    = (const float*)d_in[8];
    float* out = (float*)d_out;
    (void)in_sizes; (void)n_in; (void)out_size;

    cudaFuncSetAttribute(gemm_tma_kernel<1>,
                         cudaFuncAttributeMaxDynamicSharedMemorySize, SMEM_TOTAL);
    cudaFuncSetAttribute(gemm_tma_kernel<2>,
                         cudaFuncAttributeMaxDynamicSharedMemorySize, SMEM_TOTAL);

    TmaEncodeFn encode = nullptr;
    cudaDriverEntryPointQueryResult qr;
    cudaGetDriverEntryPointByVersion("cuTensorMapEncodeTiled", (void**)&encode,
                                     12000, cudaEnableDefault, &qr);

    __half *Wv_hi, *Wv_lo, *Wo_hi, *Wl_hi, *val_hi, *qk_hi;
    __half *vpT_hi, *qkl_hi, *attn_hi, *out2_hi, *out2_lo;
    float *attnf;
    cudaGetSymbolAddress((void**)&Wv_hi,  g_Wv_hi);  cudaGetSymbolAddress((void**)&Wv_lo, g_Wv_lo);
    cudaGetSymbolAddress((void**)&Wo_hi,  g_Wo_hi);
    cudaGetSymbolAddress((void**)&Wl_hi,  g_Wl_hi);
    cudaGetSymbolAddress((void**)&val_hi, g_val_hi);
    cudaGetSymbolAddress((void**)&qk_hi,  g_qk_hi);
    cudaGetSymbolAddress((void**)&vpT_hi, g_vpT_hi);
    cudaGetSymbolAddress((void**)&qkl_hi, g_qkl_hi);
    cudaGetSymbolAddress((void**)&attn_hi, g_attn_hi);
    cudaGetSymbolAddress((void**)&out2_hi, g_out2_hi); cudaGetSymbolAddress((void**)&out2_lo, g_out2_lo);
    cudaGetSymbolAddress((void**)&attnf, g_attn);

    dim3 blk(256);

    // 1) fused split: hi for all six operands, lo only for Wv
    split_all_kernel<<<SPLIT_BLOCKS, blk>>>(
        (const float4*)Wv, (const float4*)Wo, (const float4*)Wl,
        (const float4*)value, (const float4*)query, (const float4*)key,
        (uint2*)Wv_hi, (uint2*)Wv_lo, (uint2*)Wo_hi, (uint2*)Wl_hi,
        (uint2*)val_hi, (uint2*)qk_hi, (uint2*)(qk_hi + (long)NTOK * EMB));

    // --- tensormaps (host-side, capture-time only) ---
    CUtensorMap tWvH, tWvL, tValH, tQkH, tWlH;
    CUtensorMap tQlH, tKlH, tAtH, tVpH, tO2H, tO2L, tWoH;
    enc_tma(encode, &tWvH, Wv_hi, EMB, EMB, 1, (long)EMB * EMB);
    enc_tma(encode, &tWvL, Wv_lo, EMB, EMB, 1, (long)EMB * EMB);
    enc_tma(encode, &tValH, val_hi, EMB, LSEQ, BATCH, (long)LSEQ * EMB);
    enc_tma(encode, &tQkH, qk_hi, EMB, 2 * NTOK, 1, (long)2 * NTOK * EMB);
    enc_tma(encode, &tWlH, Wl_hi, EMB, MLM, 1, (long)MLM * EMB);
    enc_tma(encode, &tQlH, qkl_hi, MLM, LSEQ, BATCH, (long)LSEQ * MLM);
    enc_tma(encode, &tKlH, qkl_hi + (long)NTOK * MLM, MLM, LSEQ, BATCH, (long)LSEQ * MLM);
    enc_tma(encode, &tAtH, attn_hi, LSEQ, LSEQ, BATCH, (long)LSEQ * LSEQ);
    enc_tma(encode, &tVpH, vpT_hi, LSEQ, EMB, BATCH, (long)EMB * LSEQ);
    enc_tma(encode, &tO2H, out2_hi, EMB, NTOK, 1, (long)NTOK * EMB);
    enc_tma(encode, &tO2L, out2_lo, EMB, NTOK, 1, (long)NTOK * EMB);
    enc_tma(encode, &tWoH, Wo_hi, EMB, EMB, 1, (long)EMB * EMB);

    // 2) VprojT = (Wv_hi + Wv_lo) x value_hi^T + bv  -> fp16 hi only
    gemm_tma_kernel<2><<<dim3(LSEQ / TN, EMB / TM, BATCH), blk, SMEM_TOTAL>>>(
        tWvH, tWvL, tValH, tValH, nullptr, vpT_hi, nullptr,
        EMB, LSEQ, EMB, 0, 1, (long)EMB * LSEQ, bv, nullptr, 1);

    // 3) landmark logits (q|k, M=8192, N=64), 1-term + fused softmax64 -> qkl hi
    gemm_tma_kernel<1><<<dim3(1, 2 * NTOK / TM, 1), blk, SMEM_TOTAL>>>(
        tQkH, tQkH, tWlH, tWlH, nullptr, qkl_hi, nullptr,
        2 * NTOK, MLM, EMB, 0, 0, 0L, nullptr, bl, 2);

    // 4) scores S = ql_hi . kl_hi (K=64), 1-term -> fp32
    gemm_tma_kernel<1><<<dim3(LSEQ / TN, LSEQ / TM, BATCH), blk, SMEM_TOTAL>>>(
        tQlH, tQlH, tKlH, tKlH, attnf, nullptr, nullptr,
        LSEQ, LSEQ, MLM, 1, 1, (long)LSEQ * LSEQ, nullptr, nullptr, 0);

    // 5) softmax over keys -> fp16 hi only (attn >= 0: no cancellation amp)
    softmax2048_kernel<<<NTOK, blk>>>(attnf, attn_hi);

    // 6) out2 = attn_hi x vpT_hi (K=2048), 1-term -> fp16 hi/lo
    gemm_tma_kernel<1><<<dim3(EMB / TN, LSEQ / TM, BATCH), blk, SMEM_TOTAL>>>(
        tAtH, tAtH, tVpH, tVpH, nullptr, out2_hi, out2_lo,
        LSEQ, EMB, LSEQ, 1, 1, (long)LSEQ * EMB, nullptr, nullptr, 1);

    // 7) out = (out2_hi + out2_lo) x Wo_hi^T + bo -> fp32 d_out
    gemm_tma_kernel<2><<<dim3(EMB / TN, NTOK / TM, 1), blk, SMEM_TOTAL>>>(
        tO2H, tO2L, tWoH, tWoH, out, nullptr, nullptr,
        NTOK, EMB, EMB, 0, 0, 0L, nullptr, bo, 0);
}